// round 1
// baseline (speedup 1.0000x reference)
#include <cuda_runtime.h>

#define NQ 16384
#define DM 256
#define NH 8
#define DH 32
#define LN_ 32      // neighbors
#define DFF_ 1024
#define NB 16
#define LN_EPS 1e-5f

// scratch: q,k,v,attn,x,t2 (each NQ*DM) + h (NQ*DFF)
__device__ float g_scratch[6u * NQ * DM + (size_t)NQ * DFF_];

// ---------------------------------------------------------------------------
// SGEMM: C[M,Nout] = A[M,K] @ W[Nout,K]^T (+ A2@W2^T) + bias (+bias2), opt ReLU
// BM=BN=128, BK=8, 256 threads, 8x8 per thread.
// Assumes M%128==0, Nout%128==0, K%8==0 (true for all our shapes).
// ---------------------------------------------------------------------------
template <bool DUAL, bool RELU>
__global__ __launch_bounds__(256)
void sgemm_bias(const float* __restrict__ A, const float* __restrict__ W,
                const float* __restrict__ A2, const float* __restrict__ W2,
                const float* __restrict__ bias, const float* __restrict__ bias2,
                float* __restrict__ C, int M, int Nout, int K)
{
    __shared__ float As[8][128];
    __shared__ float Bs[8][128];

    const int tid = threadIdx.x;
    const int bm = blockIdx.y * 128;
    const int bn = blockIdx.x * 128;
    const int tx = tid & 15;
    const int ty = tid >> 4;

    const int lrow = tid >> 1;
    const int lcol = (tid & 1) << 2;

    float acc[8][8];
#pragma unroll
    for (int i = 0; i < 8; ++i)
#pragma unroll
        for (int j = 0; j < 8; ++j) acc[i][j] = 0.f;

    const int npass = DUAL ? 2 : 1;
    for (int pass = 0; pass < npass; ++pass) {
        const float* Ap = (DUAL && pass) ? A2 : A;
        const float* Wp = (DUAL && pass) ? W2 : W;
        for (int k0 = 0; k0 < K; k0 += 8) {
            float4 av = *(const float4*)(Ap + (size_t)(bm + lrow) * K + k0 + lcol);
            float4 wv = *(const float4*)(Wp + (size_t)(bn + lrow) * K + k0 + lcol);
            __syncthreads();
            As[lcol + 0][lrow] = av.x; As[lcol + 1][lrow] = av.y;
            As[lcol + 2][lrow] = av.z; As[lcol + 3][lrow] = av.w;
            Bs[lcol + 0][lrow] = wv.x; Bs[lcol + 1][lrow] = wv.y;
            Bs[lcol + 2][lrow] = wv.z; Bs[lcol + 3][lrow] = wv.w;
            __syncthreads();
#pragma unroll
            for (int kk = 0; kk < 8; ++kk) {
                float a[8], b[8];
                *(float4*)&a[0] = *(const float4*)&As[kk][ty * 8];
                *(float4*)&a[4] = *(const float4*)&As[kk][ty * 8 + 4];
                *(float4*)&b[0] = *(const float4*)&Bs[kk][tx * 8];
                *(float4*)&b[4] = *(const float4*)&Bs[kk][tx * 8 + 4];
#pragma unroll
                for (int i = 0; i < 8; ++i)
#pragma unroll
                    for (int j = 0; j < 8; ++j)
                        acc[i][j] += a[i] * b[j];
            }
        }
    }

    // epilogue
    float bcol[8];
#pragma unroll
    for (int j = 0; j < 8; ++j) {
        int col = bn + tx * 8 + j;
        float bb = bias[col];
        if (DUAL) bb += bias2[col];
        bcol[j] = bb;
    }
#pragma unroll
    for (int i = 0; i < 8; ++i) {
        int row = bm + ty * 8 + i;
        float4 r0, r1;
        r0.x = acc[i][0] + bcol[0]; r0.y = acc[i][1] + bcol[1];
        r0.z = acc[i][2] + bcol[2]; r0.w = acc[i][3] + bcol[3];
        r1.x = acc[i][4] + bcol[4]; r1.y = acc[i][5] + bcol[5];
        r1.z = acc[i][6] + bcol[6]; r1.w = acc[i][7] + bcol[7];
        if (RELU) {
            r0.x = fmaxf(r0.x, 0.f); r0.y = fmaxf(r0.y, 0.f);
            r0.z = fmaxf(r0.z, 0.f); r0.w = fmaxf(r0.w, 0.f);
            r1.x = fmaxf(r1.x, 0.f); r1.y = fmaxf(r1.y, 0.f);
            r1.z = fmaxf(r1.z, 0.f); r1.w = fmaxf(r1.w, 0.f);
        }
        float* cp = C + (size_t)row * Nout + bn + tx * 8;
        *(float4*)cp = r0;
        *(float4*)(cp + 4) = r1;
    }
}

// ---------------------------------------------------------------------------
// Local attention: one warp per query. 4 lanes per head, 8 dims per lane.
// logit[h,j] = scale * sum_d q[n,h,d]*k[g(n,j), h*32+d]; softmax over j;
// out[n,h,d] = sum_j p_j * v[g(n,j), h*32+d]
// ---------------------------------------------------------------------------
__global__ __launch_bounds__(256)
void attn_kernel(const float* __restrict__ q, const float* __restrict__ k,
                 const float* __restrict__ v, const int* __restrict__ kbc,
                 const int* __restrict__ ipair, const int* __restrict__ ibatch,
                 float* __restrict__ out)
{
    __shared__ int sg[8][32];
    const int warp = threadIdx.x >> 5;
    const int lane = threadIdx.x & 31;
    const int n = blockIdx.x * 8 + warp;
    const int h = lane >> 2;
    const int s = lane & 3;
    const int doff = h * 32 + s * 8;

    // batch offset (exclusive prefix sum of key_batch_cnt up to this batch)
    int b = ibatch[n];
    int off = 0;
    for (int i = 0; i < b; ++i) off += kbc[i];

    int idx = ipair[n * 32 + lane];
    unsigned mb = __ballot_sync(0xffffffffu, idx < 0);
    sg[warp][lane] = ((idx < 0) ? 0 : idx) + off;
    __syncwarp();

    const float scale = 0.17677669529663687f;  // 32^-0.5
    float qr[8];
    {
        float4 q0 = *(const float4*)&q[(size_t)n * 256 + doff];
        float4 q1 = *(const float4*)&q[(size_t)n * 256 + doff + 4];
        qr[0] = q0.x * scale; qr[1] = q0.y * scale; qr[2] = q0.z * scale; qr[3] = q0.w * scale;
        qr[4] = q1.x * scale; qr[5] = q1.y * scale; qr[6] = q1.z * scale; qr[7] = q1.w * scale;
    }

    float lg[32];
#pragma unroll
    for (int j = 0; j < 32; ++j) {
        const float* kr = &k[(size_t)sg[warp][j] * 256 + doff];
        float4 k0 = *(const float4*)kr;
        float4 k1 = *(const float4*)(kr + 4);
        float t = qr[0] * k0.x + qr[1] * k0.y + qr[2] * k0.z + qr[3] * k0.w
                + qr[4] * k1.x + qr[5] * k1.y + qr[6] * k1.z + qr[7] * k1.w;
        t += __shfl_xor_sync(0xffffffffu, t, 1);
        t += __shfl_xor_sync(0xffffffffu, t, 2);
        lg[j] = ((mb >> j) & 1u) ? -1e9f : t;
    }

    float m = lg[0];
#pragma unroll
    for (int j = 1; j < 32; ++j) m = fmaxf(m, lg[j]);
    float sum = 0.f;
#pragma unroll
    for (int j = 0; j < 32; ++j) { lg[j] = __expf(lg[j] - m); sum += lg[j]; }
    float rinv = 1.f / sum;

    float acc[8];
#pragma unroll
    for (int i = 0; i < 8; ++i) acc[i] = 0.f;
#pragma unroll
    for (int j = 0; j < 32; ++j) {
        const float* vr = &v[(size_t)sg[warp][j] * 256 + doff];
        float4 v0 = *(const float4*)vr;
        float4 v1 = *(const float4*)(vr + 4);
        float p = lg[j] * rinv;
        acc[0] += p * v0.x; acc[1] += p * v0.y; acc[2] += p * v0.z; acc[3] += p * v0.w;
        acc[4] += p * v1.x; acc[5] += p * v1.y; acc[6] += p * v1.z; acc[7] += p * v1.w;
    }

    float* op = &out[(size_t)n * 256 + doff];
    *(float4*)op = make_float4(acc[0], acc[1], acc[2], acc[3]);
    *(float4*)(op + 4) = make_float4(acc[4], acc[5], acc[6], acc[7]);
}

// ---------------------------------------------------------------------------
// out = LayerNorm(a + b) * g + be ; one warp per row (D=256, 8 elems/lane)
// ---------------------------------------------------------------------------
__global__ __launch_bounds__(256)
void residual_ln(const float* __restrict__ a, const float* __restrict__ bsrc,
                 const float* __restrict__ g, const float* __restrict__ be,
                 float* __restrict__ out)
{
    const int warp = threadIdx.x >> 5;
    const int lane = threadIdx.x & 31;
    const int n = blockIdx.x * 8 + warp;
    const int base = lane * 8;

    float x[8];
    {
        const float4* pa0 = (const float4*)&a[(size_t)n * 256 + base];
        const float4* pb0 = (const float4*)&bsrc[(size_t)n * 256 + base];
        float4 a0 = pa0[0], a1 = pa0[1];
        float4 b0 = pb0[0], b1 = pb0[1];
        x[0] = a0.x + b0.x; x[1] = a0.y + b0.y; x[2] = a0.z + b0.z; x[3] = a0.w + b0.w;
        x[4] = a1.x + b1.x; x[5] = a1.y + b1.y; x[6] = a1.z + b1.z; x[7] = a1.w + b1.w;
    }
    float s = 0.f;
#pragma unroll
    for (int i = 0; i < 8; ++i) s += x[i];
#pragma unroll
    for (int o = 16; o > 0; o >>= 1) s += __shfl_xor_sync(0xffffffffu, s, o);
    float mean = s * (1.f / 256.f);

    float vs = 0.f;
#pragma unroll
    for (int i = 0; i < 8; ++i) { float d = x[i] - mean; vs += d * d; }
#pragma unroll
    for (int o = 16; o > 0; o >>= 1) vs += __shfl_xor_sync(0xffffffffu, vs, o);
    float inv = rsqrtf(vs * (1.f / 256.f) + LN_EPS);

    float4 gg0 = *(const float4*)&g[base];
    float4 gg1 = *(const float4*)&g[base + 4];
    float4 bb0 = *(const float4*)&be[base];
    float4 bb1 = *(const float4*)&be[base + 4];

    float4 r0, r1;
    r0.x = (x[0] - mean) * inv * gg0.x + bb0.x;
    r0.y = (x[1] - mean) * inv * gg0.y + bb0.y;
    r0.z = (x[2] - mean) * inv * gg0.z + bb0.z;
    r0.w = (x[3] - mean) * inv * gg0.w + bb0.w;
    r1.x = (x[4] - mean) * inv * gg1.x + bb1.x;
    r1.y = (x[5] - mean) * inv * gg1.y + bb1.y;
    r1.z = (x[6] - mean) * inv * gg1.z + bb1.z;
    r1.w = (x[7] - mean) * inv * gg1.w + bb1.w;

    float* op = &out[(size_t)n * 256 + base];
    *(float4*)op = r0;
    *(float4*)(op + 4) = r1;
}

// ---------------------------------------------------------------------------
extern "C" void kernel_launch(void* const* d_in, const int* in_sizes, int n_in,
                              void* d_out, int out_size)
{
    const float* tgt  = (const float*)d_in[0];
    const float* mem  = (const float*)d_in[1];
    const float* pos  = (const float*)d_in[2];
    const int*   kbc  = (const int*)d_in[3];
    const int*   ipair  = (const int*)d_in[4];
    const int*   ibatch = (const int*)d_in[5];
    const float* Wq  = (const float*)d_in[6];
    const float* bq  = (const float*)d_in[7];
    const float* Wkc = (const float*)d_in[8];
    const float* bkc = (const float*)d_in[9];
    const float* Wkp = (const float*)d_in[10];
    const float* bkp = (const float*)d_in[11];
    const float* Wv  = (const float*)d_in[12];
    const float* bv  = (const float*)d_in[13];
    const float* Wo  = (const float*)d_in[14];
    const float* bo  = (const float*)d_in[15];
    const float* W1  = (const float*)d_in[16];
    const float* b1  = (const float*)d_in[17];
    const float* W2  = (const float*)d_in[18];
    const float* b2  = (const float*)d_in[19];
    const float* g2  = (const float*)d_in[20];
    const float* be2 = (const float*)d_in[21];
    const float* g3  = (const float*)d_in[22];
    const float* be3 = (const float*)d_in[23];
    float* out = (float*)d_out;

    float* scratch = nullptr;
    cudaGetSymbolAddress((void**)&scratch, g_scratch);
    float* q_   = scratch + 0u * NQ * DM;
    float* k_   = scratch + 1u * NQ * DM;
    float* v_   = scratch + 2u * NQ * DM;
    float* at_  = scratch + 3u * NQ * DM;
    float* x_   = scratch + 4u * NQ * DM;
    float* t2_  = scratch + 5u * NQ * DM;
    float* h_   = scratch + 6u * NQ * DM;

    dim3 blk(256);
    dim3 gP(DM / 128, NQ / 128);     // D x D projections
    dim3 gF1(DFF_ / 128, NQ / 128);  // FFN up
    dim3 gF2(DM / 128, NQ / 128);    // FFN down

    // q = tgt @ Wq^T + bq
    sgemm_bias<false, false><<<gP, blk>>>(tgt, Wq, nullptr, nullptr, bq, nullptr,
                                          q_, NQ, DM, DM);
    // k = mem @ Wkc^T + pos @ Wkp^T + bkc + bkp
    sgemm_bias<true, false><<<gP, blk>>>(mem, Wkc, pos, Wkp, bkc, bkp,
                                         k_, NQ, DM, DM);
    // v = mem @ Wv^T + bv
    sgemm_bias<false, false><<<gP, blk>>>(mem, Wv, nullptr, nullptr, bv, nullptr,
                                          v_, NQ, DM, DM);
    // attention
    attn_kernel<<<NQ / 8, blk>>>(q_, k_, v_, kbc, ipair, ibatch, at_);
    // tgt2 = attn @ Wo^T + bo
    sgemm_bias<false, false><<<gP, blk>>>(at_, Wo, nullptr, nullptr, bo, nullptr,
                                          t2_, NQ, DM, DM);
    // x = LN(tgt + tgt2)
    residual_ln<<<NQ / 8, blk>>>(tgt, t2_, g2, be2, x_);
    // h = relu(x @ W1^T + b1)
    sgemm_bias<false, true><<<gF1, blk>>>(x_, W1, nullptr, nullptr, b1, nullptr,
                                          h_, NQ, DFF_, DM);
    // y = h @ W2^T + b2
    sgemm_bias<false, false><<<gF2, blk>>>(h_, W2, nullptr, nullptr, b2, nullptr,
                                           t2_, NQ, DM, DFF_);
    // out = LN(x + y)
    residual_ln<<<NQ / 8, blk>>>(x_, t2_, g3, be3, out);
}

// round 3
// speedup vs baseline: 1.3182x; 1.3182x over previous
#include <cuda_runtime.h>
#include <cuda_bf16.h>
#include <cstdint>

#define NQ 16384
#define DM 256
#define DFF_ 1024
#define LN_EPS 1e-5f

// ---------------------------------------------------------------------------
// scratch
// ---------------------------------------------------------------------------
// fp32: q,k,v,t2,x   (each NQ*DM)
__device__ float g_f32[5u * NQ * DM];

// bf16 hi/lo pools (element offsets below)
#define OFF_TGT 0u
#define OFF_MEM 4194304u
#define OFF_POS 8388608u
#define OFF_AT  12582912u
#define OFF_X   16777216u
#define OFF_H   20971520u
#define OFF_WQ  37748736u
#define OFF_WKC 37814272u
#define OFF_WKP 37879808u
#define OFF_WV  37945344u
#define OFF_WO  38010880u
#define OFF_W1  38076416u
#define OFF_W2  38338560u
#define TOT_BF  38600704u
__device__ __nv_bfloat16 g_hi[TOT_BF];
__device__ __nv_bfloat16 g_lo[TOT_BF];

// ---------------------------------------------------------------------------
// helpers
// ---------------------------------------------------------------------------
__device__ __forceinline__ uint32_t smem_u32(const void* p) {
    uint32_t a;
    asm("{ .reg .u64 t; cvta.to.shared.u64 t, %1; cvt.u32.u64 %0, t; }"
        : "=r"(a) : "l"(p));
    return a;
}
__device__ __forceinline__ void cpa16(uint32_t dst, const void* src) {
    asm volatile("cp.async.cg.shared.global [%0], [%1], 16;"
                 :: "r"(dst), "l"(src) : "memory");
}
#define CP_COMMIT() asm volatile("cp.async.commit_group;" ::: "memory")
#define CP_WAIT(n)  asm volatile("cp.async.wait_group %0;" :: "n"(n) : "memory")

#define LDSM4(r, addr) \
    asm volatile("ldmatrix.sync.aligned.m8n8.x4.shared.b16 {%0,%1,%2,%3}, [%4];" \
        : "=r"((r)[0]), "=r"((r)[1]), "=r"((r)[2]), "=r"((r)[3]) : "r"(addr))

#define MMA_BF16(d, a, b0, b1) \
    asm volatile("mma.sync.aligned.m16n8k16.row.col.f32.bf16.bf16.f32 " \
        "{%0,%1,%2,%3}, {%4,%5,%6,%7}, {%8,%9}, {%0,%1,%2,%3};" \
        : "+f"((d)[0]), "+f"((d)[1]), "+f"((d)[2]), "+f"((d)[3]) \
        : "r"((a)[0]), "r"((a)[1]), "r"((a)[2]), "r"((a)[3]), "r"(b0), "r"(b1))

__device__ __forceinline__ void split1(float x, __nv_bfloat16& h, __nv_bfloat16& l) {
    h = __float2bfloat16(x);
    l = __float2bfloat16(x - __bfloat162float(h));
}

// ---------------------------------------------------------------------------
// Conversion: fp32 -> (hi,lo) bf16, 10 tensors via blockIdx.y
// ---------------------------------------------------------------------------
__global__ __launch_bounds__(256)
void conv_all(const float* s0, const float* s1, const float* s2, const float* s3,
              const float* s4, const float* s5, const float* s6, const float* s7,
              const float* s8, const float* s9,
              __nv_bfloat16* hi, __nv_bfloat16* lo)
{
    const int t = blockIdx.y;
    const unsigned narr[10] = {4194304u, 4194304u, 4194304u, 65536u, 65536u,
                               65536u, 65536u, 65536u, 262144u, 262144u};
    const unsigned offarr[10] = {OFF_TGT, OFF_MEM, OFF_POS, OFF_WQ, OFF_WKC,
                                 OFF_WKP, OFF_WV, OFF_WO, OFF_W1, OFF_W2};
    const float* srcs[10] = {s0, s1, s2, s3, s4, s5, s6, s7, s8, s9};
    unsigned i = (blockIdx.x * 256u + threadIdx.x) * 4u;
    if (i >= narr[t]) return;
    const float* src = srcs[t];
    size_t base = offarr[t] + i;
    float4 v = *(const float4*)(src + i);
    __nv_bfloat16 h0, h1, h2, h3, l0, l1, l2, l3;
    split1(v.x, h0, l0); split1(v.y, h1, l1);
    split1(v.z, h2, l2); split1(v.w, h3, l3);
    __nv_bfloat162 p;
    p.x = h0; p.y = h1; *(__nv_bfloat162*)(hi + base) = p;
    p.x = h2; p.y = h3; *(__nv_bfloat162*)(hi + base + 2) = p;
    p.x = l0; p.y = l1; *(__nv_bfloat162*)(lo + base) = p;
    p.x = l2; p.y = l3; *(__nv_bfloat162*)(lo + base + 2) = p;
}

// ---------------------------------------------------------------------------
// HMMA bf16x3 GEMM: C[M,Nout] = A[M,K] @ W[Nout,K]^T (+A2@W2^T) + bias
// 128x128 CTA tile, BK=64, 8 warps (each 64x32), 2-stage cp.async pipeline.
// smem per stage: Ahi,Alo,Whi,Wlo each [128][64] bf16 padded to 72 (144B rows).
// ---------------------------------------------------------------------------
#define PART_SZ 18432u              // 128 * 144
#define STAGE_SZ 73728u             // 4 * PART_SZ
#define SMEM_BYTES (2u * STAGE_SZ)  // 147456

template <bool DUAL, bool RELU, bool OUTBF>
__global__ __launch_bounds__(256)
void gemm_mma(const __nv_bfloat16* __restrict__ Ahi, const __nv_bfloat16* __restrict__ Alo,
              const __nv_bfloat16* __restrict__ Whi, const __nv_bfloat16* __restrict__ Wlo,
              const __nv_bfloat16* __restrict__ A2hi, const __nv_bfloat16* __restrict__ A2lo,
              const __nv_bfloat16* __restrict__ W2hi, const __nv_bfloat16* __restrict__ W2lo,
              const float* __restrict__ bias, const float* __restrict__ bias2,
              float* __restrict__ C,
              __nv_bfloat16* __restrict__ Chi, __nv_bfloat16* __restrict__ Clo,
              int M, int Nout, int K)
{
    extern __shared__ char smem[];
    const uint32_t sbase = smem_u32(smem);
    const int tid = threadIdx.x;
    const int wid = tid >> 5;
    const int lane = tid & 31;
    const int bm = blockIdx.y * 128;
    const int bn = blockIdx.x * 128;
    const int wm = (wid & 1) * 64;       // warp row base within tile
    const int wn = (wid >> 1) * 32;      // warp col base within tile

    const int kcPer = K >> 6;
    const int nchunk = DUAL ? kcPer * 2 : kcPer;

    float acc[4][4][4];
#pragma unroll
    for (int a = 0; a < 4; ++a)
#pragma unroll
        for (int b = 0; b < 4; ++b)
#pragma unroll
            for (int c = 0; c < 4; ++c) acc[a][b][c] = 0.f;

    auto loadChunk = [&](int c) {
        const uint32_t stage = sbase + (uint32_t)(c & 1) * STAGE_SZ;
        const bool pair = DUAL && (c >= kcPer);
        const int kc = pair ? c - kcPer : c;
        const __nv_bfloat16* srcs[4] = {
            pair ? A2hi : Ahi, pair ? A2lo : Alo,
            pair ? W2hi : Whi, pair ? W2lo : Wlo };
#pragma unroll
        for (int p = 0; p < 4; ++p) {
            const __nv_bfloat16* src = srcs[p];
            const int rbase = (p < 2) ? bm : bn;
            const uint32_t pdst = stage + p * PART_SZ;
#pragma unroll
            for (int it = 0; it < 4; ++it) {
                int i = tid + it * 256;
                int row = i >> 3, u = i & 7;
                cpa16(pdst + row * 144 + u * 16,
                      src + (size_t)(rbase + row) * K + kc * 64 + u * 8);
            }
        }
        CP_COMMIT();
    };

    const uint32_t laneOff = (uint32_t)((lane & 15) * 144 + (lane >> 4) * 16);

    auto computeChunk = [&](int s) {
        const uint32_t stage = sbase + (uint32_t)s * STAGE_SZ;
        const uint32_t aH = stage + laneOff;
        const uint32_t aL = stage + PART_SZ + laneOff;
        const uint32_t wH = stage + 2 * PART_SZ + laneOff;
        const uint32_t wL = stage + 3 * PART_SZ + laneOff;
#pragma unroll
        for (int ks = 0; ks < 4; ++ks) {
            const uint32_t kb = ks * 32;   // 16 bf16 = 32 bytes
            uint32_t ah[4][4], al[4][4], bh[2][4], bl[2][4];
#pragma unroll
            for (int mt = 0; mt < 4; ++mt) {
                LDSM4(ah[mt], aH + (wm + mt * 16) * 144 + kb);
                LDSM4(al[mt], aL + (wm + mt * 16) * 144 + kb);
            }
#pragma unroll
            for (int np = 0; np < 2; ++np) {
                LDSM4(bh[np], wH + (wn + np * 16) * 144 + kb);
                LDSM4(bl[np], wL + (wn + np * 16) * 144 + kb);
            }
#pragma unroll
            for (int mt = 0; mt < 4; ++mt) {
#pragma unroll
                for (int nt = 0; nt < 4; ++nt) {
                    const int np = nt >> 1;
                    const int o0 = (nt & 1);       // reg idx for k0-7 part
                    const int o1 = o0 + 2;         // reg idx for k8-15 part
                    MMA_BF16(acc[mt][nt], ah[mt], bh[np][o0], bh[np][o1]);
                    MMA_BF16(acc[mt][nt], ah[mt], bl[np][o0], bl[np][o1]);
                    MMA_BF16(acc[mt][nt], al[mt], bh[np][o0], bh[np][o1]);
                }
            }
        }
    };

    // pipeline: prefetch depth 1
    loadChunk(0);
    for (int c = 0; c < nchunk; ++c) {
        if (c + 1 < nchunk) {
            loadChunk(c + 1);
            CP_WAIT(1);
        } else {
            CP_WAIT(0);
        }
        __syncthreads();
        computeChunk(c & 1);
        __syncthreads();
    }

    // epilogue: registers -> gmem directly
    float bcol[4][2];
#pragma unroll
    for (int nt = 0; nt < 4; ++nt) {
        int col = bn + wn + nt * 8 + (lane & 3) * 2;
        float b0 = bias[col], b1 = bias[col + 1];
        if (DUAL) { b0 += bias2[col]; b1 += bias2[col + 1]; }
        bcol[nt][0] = b0; bcol[nt][1] = b1;
    }
#pragma unroll
    for (int mt = 0; mt < 4; ++mt) {
        int row0 = bm + wm + mt * 16 + (lane >> 2);
#pragma unroll
        for (int nt = 0; nt < 4; ++nt) {
            int col = bn + wn + nt * 8 + (lane & 3) * 2;
#pragma unroll
            for (int half = 0; half < 2; ++half) {
                int row = row0 + half * 8;
                float v0 = acc[mt][nt][half * 2 + 0] + bcol[nt][0];
                float v1 = acc[mt][nt][half * 2 + 1] + bcol[nt][1];
                if (RELU) { v0 = fmaxf(v0, 0.f); v1 = fmaxf(v1, 0.f); }
                size_t go = (size_t)row * Nout + col;
                if (OUTBF) {
                    __nv_bfloat16 h0, h1, l0, l1;
                    split1(v0, h0, l0); split1(v1, h1, l1);
                    __nv_bfloat162 p;
                    p.x = h0; p.y = h1; *(__nv_bfloat162*)(Chi + go) = p;
                    p.x = l0; p.y = l1; *(__nv_bfloat162*)(Clo + go) = p;
                } else {
                    *(float2*)(C + go) = make_float2(v0, v1);
                }
            }
        }
    }
}

// ---------------------------------------------------------------------------
// Local attention: one warp per query; writes hi/lo bf16 output.
// ---------------------------------------------------------------------------
__global__ __launch_bounds__(256)
void attn_kernel(const float* __restrict__ q, const float* __restrict__ k,
                 const float* __restrict__ v, const int* __restrict__ kbc,
                 const int* __restrict__ ipair, const int* __restrict__ ibatch,
                 __nv_bfloat16* __restrict__ ohi, __nv_bfloat16* __restrict__ olo)
{
    __shared__ int sg[8][32];
    const int warp = threadIdx.x >> 5;
    const int lane = threadIdx.x & 31;
    const int n = blockIdx.x * 8 + warp;
    const int h = lane >> 2;
    const int s = lane & 3;
    const int doff = h * 32 + s * 8;

    int b = ibatch[n];
    int off = 0;
    for (int i = 0; i < b; ++i) off += kbc[i];

    int idx = ipair[n * 32 + lane];
    unsigned mb = __ballot_sync(0xffffffffu, idx < 0);
    sg[warp][lane] = ((idx < 0) ? 0 : idx) + off;
    __syncwarp();

    const float scale = 0.17677669529663687f;
    float qr[8];
    {
        float4 q0 = *(const float4*)&q[(size_t)n * 256 + doff];
        float4 q1 = *(const float4*)&q[(size_t)n * 256 + doff + 4];
        qr[0] = q0.x * scale; qr[1] = q0.y * scale; qr[2] = q0.z * scale; qr[3] = q0.w * scale;
        qr[4] = q1.x * scale; qr[5] = q1.y * scale; qr[6] = q1.z * scale; qr[7] = q1.w * scale;
    }

    float lg[32];
#pragma unroll
    for (int j = 0; j < 32; ++j) {
        const float* kr = &k[(size_t)sg[warp][j] * 256 + doff];
        float4 k0 = *(const float4*)kr;
        float4 k1 = *(const float4*)(kr + 4);
        float t = qr[0] * k0.x + qr[1] * k0.y + qr[2] * k0.z + qr[3] * k0.w
                + qr[4] * k1.x + qr[5] * k1.y + qr[6] * k1.z + qr[7] * k1.w;
        t += __shfl_xor_sync(0xffffffffu, t, 1);
        t += __shfl_xor_sync(0xffffffffu, t, 2);
        lg[j] = ((mb >> j) & 1u) ? -1e9f : t;
    }

    float m = lg[0];
#pragma unroll
    for (int j = 1; j < 32; ++j) m = fmaxf(m, lg[j]);
    float sum = 0.f;
#pragma unroll
    for (int j = 0; j < 32; ++j) { lg[j] = __expf(lg[j] - m); sum += lg[j]; }
    float rinv = 1.f / sum;

    float acc[8];
#pragma unroll
    for (int i = 0; i < 8; ++i) acc[i] = 0.f;
#pragma unroll
    for (int j = 0; j < 32; ++j) {
        const float* vr = &v[(size_t)sg[warp][j] * 256 + doff];
        float4 v0 = *(const float4*)vr;
        float4 v1 = *(const float4*)(vr + 4);
        float p = lg[j] * rinv;
        acc[0] += p * v0.x; acc[1] += p * v0.y; acc[2] += p * v0.z; acc[3] += p * v0.w;
        acc[4] += p * v1.x; acc[5] += p * v1.y; acc[6] += p * v1.z; acc[7] += p * v1.w;
    }

    size_t o = (size_t)n * 256 + doff;
#pragma unroll
    for (int i = 0; i < 8; i += 2) {
        __nv_bfloat16 h0, h1, l0, l1;
        split1(acc[i], h0, l0);
        split1(acc[i + 1], h1, l1);
        __nv_bfloat162 p;
        p.x = h0; p.y = h1; *(__nv_bfloat162*)(ohi + o + i) = p;
        p.x = l0; p.y = l1; *(__nv_bfloat162*)(olo + o + i) = p;
    }
}

// ---------------------------------------------------------------------------
// out = LayerNorm(a + b); optionally also writes hi/lo bf16 copy.
// ---------------------------------------------------------------------------
template <bool OUTBF>
__global__ __launch_bounds__(256)
void residual_ln(const float* __restrict__ a, const float* __restrict__ bsrc,
                 const float* __restrict__ g, const float* __restrict__ be,
                 float* __restrict__ out,
                 __nv_bfloat16* __restrict__ ohi, __nv_bfloat16* __restrict__ olo)
{
    const int warp = threadIdx.x >> 5;
    const int lane = threadIdx.x & 31;
    const int n = blockIdx.x * 8 + warp;
    const int base = lane * 8;

    float x[8];
    {
        const float4* pa0 = (const float4*)&a[(size_t)n * 256 + base];
        const float4* pb0 = (const float4*)&bsrc[(size_t)n * 256 + base];
        float4 a0 = pa0[0], a1 = pa0[1];
        float4 b0 = pb0[0], b1 = pb0[1];
        x[0] = a0.x + b0.x; x[1] = a0.y + b0.y; x[2] = a0.z + b0.z; x[3] = a0.w + b0.w;
        x[4] = a1.x + b1.x; x[5] = a1.y + b1.y; x[6] = a1.z + b1.z; x[7] = a1.w + b1.w;
    }
    float s = 0.f;
#pragma unroll
    for (int i = 0; i < 8; ++i) s += x[i];
#pragma unroll
    for (int o = 16; o > 0; o >>= 1) s += __shfl_xor_sync(0xffffffffu, s, o);
    float mean = s * (1.f / 256.f);

    float vs = 0.f;
#pragma unroll
    for (int i = 0; i < 8; ++i) { float d = x[i] - mean; vs += d * d; }
#pragma unroll
    for (int o = 16; o > 0; o >>= 1) vs += __shfl_xor_sync(0xffffffffu, vs, o);
    float inv = rsqrtf(vs * (1.f / 256.f) + LN_EPS);

    float4 gg0 = *(const float4*)&g[base];
    float4 gg1 = *(const float4*)&g[base + 4];
    float4 bb0 = *(const float4*)&be[base];
    float4 bb1 = *(const float4*)&be[base + 4];

    float r[8];
    r[0] = (x[0] - mean) * inv * gg0.x + bb0.x;
    r[1] = (x[1] - mean) * inv * gg0.y + bb0.y;
    r[2] = (x[2] - mean) * inv * gg0.z + bb0.z;
    r[3] = (x[3] - mean) * inv * gg0.w + bb0.w;
    r[4] = (x[4] - mean) * inv * gg1.x + bb1.x;
    r[5] = (x[5] - mean) * inv * gg1.y + bb1.y;
    r[6] = (x[6] - mean) * inv * gg1.z + bb1.z;
    r[7] = (x[7] - mean) * inv * gg1.w + bb1.w;

    size_t o = (size_t)n * 256 + base;
    *(float4*)(out + o) = make_float4(r[0], r[1], r[2], r[3]);
    *(float4*)(out + o + 4) = make_float4(r[4], r[5], r[6], r[7]);

    if (OUTBF) {
#pragma unroll
        for (int i = 0; i < 8; i += 2) {
            __nv_bfloat16 h0, h1, l0, l1;
            split1(r[i], h0, l0);
            split1(r[i + 1], h1, l1);
            __nv_bfloat162 p;
            p.x = h0; p.y = h1; *(__nv_bfloat162*)(ohi + o + i) = p;
            p.x = l0; p.y = l1; *(__nv_bfloat162*)(olo + o + i) = p;
        }
    }
}

// ---------------------------------------------------------------------------
extern "C" void kernel_launch(void* const* d_in, const int* in_sizes, int n_in,
                              void* d_out, int out_size)
{
    const float* tgt  = (const float*)d_in[0];
    const float* mem  = (const float*)d_in[1];
    const float* pos  = (const float*)d_in[2];
    const int*   kbc  = (const int*)d_in[3];
    const int*   ipair  = (const int*)d_in[4];
    const int*   ibatch = (const int*)d_in[5];
    const float* Wq  = (const float*)d_in[6];
    const float* bq  = (const float*)d_in[7];
    const float* Wkc = (const float*)d_in[8];
    const float* bkc = (const float*)d_in[9];
    const float* Wkp = (const float*)d_in[10];
    const float* bkp = (const float*)d_in[11];
    const float* Wv  = (const float*)d_in[12];
    const float* bv  = (const float*)d_in[13];
    const float* Wo  = (const float*)d_in[14];
    const float* bo  = (const float*)d_in[15];
    const float* W1  = (const float*)d_in[16];
    const float* b1  = (const float*)d_in[17];
    const float* W2  = (const float*)d_in[18];
    const float* b2  = (const float*)d_in[19];
    const float* g2  = (const float*)d_in[20];
    const float* be2 = (const float*)d_in[21];
    const float* g3  = (const float*)d_in[22];
    const float* be3 = (const float*)d_in[23];
    float* out = (float*)d_out;

    float* f32 = nullptr;
    __nv_bfloat16* hi = nullptr;
    __nv_bfloat16* lo = nullptr;
    cudaGetSymbolAddress((void**)&f32, g_f32);
    cudaGetSymbolAddress((void**)&hi, g_hi);
    cudaGetSymbolAddress((void**)&lo, g_lo);

    float* q_  = f32 + 0u * NQ * DM;
    float* k_  = f32 + 1u * NQ * DM;
    float* v_  = f32 + 2u * NQ * DM;
    float* t2_ = f32 + 3u * NQ * DM;
    float* x_  = f32 + 4u * NQ * DM;

    cudaFuncSetAttribute(gemm_mma<false, false, false>,
                         cudaFuncAttributeMaxDynamicSharedMemorySize, SMEM_BYTES);
    cudaFuncSetAttribute(gemm_mma<true, false, false>,
                         cudaFuncAttributeMaxDynamicSharedMemorySize, SMEM_BYTES);
    cudaFuncSetAttribute(gemm_mma<false, true, true>,
                         cudaFuncAttributeMaxDynamicSharedMemorySize, SMEM_BYTES);

    // converts
    conv_all<<<dim3(4096, 10), 256>>>(tgt, mem, pos, Wq, Wkc, Wkp, Wv, Wo, W1, W2, hi, lo);

    dim3 blk(256);
    dim3 gP(2, 128);    // Nout=256
    dim3 gF1(8, 128);   // Nout=1024

    // q = tgt @ Wq^T + bq
    gemm_mma<false, false, false><<<gP, blk, SMEM_BYTES>>>(
        hi + OFF_TGT, lo + OFF_TGT, hi + OFF_WQ, lo + OFF_WQ,
        nullptr, nullptr, nullptr, nullptr, bq, nullptr,
        q_, nullptr, nullptr, NQ, DM, DM);
    // k = mem @ Wkc^T + pos @ Wkp^T + bkc + bkp
    gemm_mma<true, false, false><<<gP, blk, SMEM_BYTES>>>(
        hi + OFF_MEM, lo + OFF_MEM, hi + OFF_WKC, lo + OFF_WKC,
        hi + OFF_POS, lo + OFF_POS, hi + OFF_WKP, lo + OFF_WKP, bkc, bkp,
        k_, nullptr, nullptr, NQ, DM, DM);
    // v = mem @ Wv^T + bv
    gemm_mma<false, false, false><<<gP, blk, SMEM_BYTES>>>(
        hi + OFF_MEM, lo + OFF_MEM, hi + OFF_WV, lo + OFF_WV,
        nullptr, nullptr, nullptr, nullptr, bv, nullptr,
        v_, nullptr, nullptr, NQ, DM, DM);
    // attention -> at (hi/lo)
    attn_kernel<<<NQ / 8, blk>>>(q_, k_, v_, kbc, ipair, ibatch, hi + OFF_AT, lo + OFF_AT);
    // t2 = at @ Wo^T + bo
    gemm_mma<false, false, false><<<gP, blk, SMEM_BYTES>>>(
        hi + OFF_AT, lo + OFF_AT, hi + OFF_WO, lo + OFF_WO,
        nullptr, nullptr, nullptr, nullptr, bo, nullptr,
        t2_, nullptr, nullptr, NQ, DM, DM);
    // x = LN(tgt + t2), also hi/lo
    residual_ln<true><<<NQ / 8, blk>>>(tgt, t2_, g2, be2, x_, hi + OFF_X, lo + OFF_X);
    // h = relu(x @ W1^T + b1) -> hi/lo only
    gemm_mma<false, true, true><<<gF1, blk, SMEM_BYTES>>>(
        hi + OFF_X, lo + OFF_X, hi + OFF_W1, lo + OFF_W1,
        nullptr, nullptr, nullptr, nullptr, b1, nullptr,
        nullptr, hi + OFF_H, lo + OFF_H, NQ, DFF_, DM);
    // y = h @ W2^T + b2
    gemm_mma<false, false, false><<<gP, blk, SMEM_BYTES>>>(
        hi + OFF_H, lo + OFF_H, hi + OFF_W2, lo + OFF_W2,
        nullptr, nullptr, nullptr, nullptr, b2, nullptr,
        t2_, nullptr, nullptr, NQ, DM, DFF_);
    // out = LN(x + y)
    residual_ln<false><<<NQ / 8, blk>>>(x_, t2_, g3, be3, out, nullptr, nullptr);
}

// round 4
// speedup vs baseline: 1.4809x; 1.1234x over previous
#include <cuda_runtime.h>
#include <cuda_bf16.h>
#include <cuda_fp16.h>
#include <cstdint>

#define NQ 16384
#define DM 256
#define DFF_ 1024
#define LN_EPS 1e-5f

// ---------------------------------------------------------------------------
// scratch
// ---------------------------------------------------------------------------
// fp32: q,t2,x   (each NQ*DM)
__device__ float g_f32[3u * NQ * DM];
// fp16: k,v
__device__ __half g_half[2u * NQ * DM];

// bf16 hi/lo pools (element offsets below)
#define OFF_TGT 0u
#define OFF_MEM 4194304u
#define OFF_POS 8388608u
#define OFF_AT  12582912u
#define OFF_X   16777216u
#define OFF_H   20971520u
#define OFF_WQ  37748736u
#define OFF_WKC 37814272u
#define OFF_WKP 37879808u
#define OFF_WV  37945344u
#define OFF_WO  38010880u
#define OFF_W1  38076416u
#define OFF_W2  38338560u
#define TOT_BF  38600704u
__device__ __nv_bfloat16 g_hi[TOT_BF];
__device__ __nv_bfloat16 g_lo[TOT_BF];

// ---------------------------------------------------------------------------
// helpers
// ---------------------------------------------------------------------------
__device__ __forceinline__ uint32_t smem_u32(const void* p) {
    uint32_t a;
    asm("{ .reg .u64 t; cvta.to.shared.u64 t, %1; cvt.u32.u64 %0, t; }"
        : "=r"(a) : "l"(p));
    return a;
}
__device__ __forceinline__ void cpa16(uint32_t dst, const void* src) {
    asm volatile("cp.async.cg.shared.global [%0], [%1], 16;"
                 :: "r"(dst), "l"(src) : "memory");
}
#define CP_COMMIT() asm volatile("cp.async.commit_group;" ::: "memory")
#define CP_WAIT(n)  asm volatile("cp.async.wait_group %0;" :: "n"(n) : "memory")

#define LDSM4(r, addr) \
    asm volatile("ldmatrix.sync.aligned.m8n8.x4.shared.b16 {%0,%1,%2,%3}, [%4];" \
        : "=r"((r)[0]), "=r"((r)[1]), "=r"((r)[2]), "=r"((r)[3]) : "r"(addr))

#define MMA_BF16(d, a, b0, b1) \
    asm volatile("mma.sync.aligned.m16n8k16.row.col.f32.bf16.bf16.f32 " \
        "{%0,%1,%2,%3}, {%4,%5,%6,%7}, {%8,%9}, {%0,%1,%2,%3};" \
        : "+f"((d)[0]), "+f"((d)[1]), "+f"((d)[2]), "+f"((d)[3]) \
        : "r"((a)[0]), "r"((a)[1]), "r"((a)[2]), "r"((a)[3]), "r"(b0), "r"(b1))

__device__ __forceinline__ void split1(float x, __nv_bfloat16& h, __nv_bfloat16& l) {
    h = __float2bfloat16(x);
    l = __float2bfloat16(x - __bfloat162float(h));
}

// swizzled smem byte offset for (row, chunk16B) with 64B rows (BK=32 bf16)
__device__ __forceinline__ uint32_t swzoff(int row, int ch) {
    return (uint32_t)(row * 64 + ((ch ^ ((row >> 1) & 3)) << 4));
}

// ---------------------------------------------------------------------------
// Conversion: fp32 -> (hi,lo) bf16, 10 tensors via blockIdx.y
// ---------------------------------------------------------------------------
__global__ __launch_bounds__(256)
void conv_all(const float* s0, const float* s1, const float* s2, const float* s3,
              const float* s4, const float* s5, const float* s6, const float* s7,
              const float* s8, const float* s9,
              __nv_bfloat16* hi, __nv_bfloat16* lo)
{
    const int t = blockIdx.y;
    const unsigned narr[10] = {4194304u, 4194304u, 4194304u, 65536u, 65536u,
                               65536u, 65536u, 65536u, 262144u, 262144u};
    const unsigned offarr[10] = {OFF_TGT, OFF_MEM, OFF_POS, OFF_WQ, OFF_WKC,
                                 OFF_WKP, OFF_WV, OFF_WO, OFF_W1, OFF_W2};
    const float* srcs[10] = {s0, s1, s2, s3, s4, s5, s6, s7, s8, s9};
    unsigned i = (blockIdx.x * 256u + threadIdx.x) * 4u;
    if (i >= narr[t]) return;
    const float* src = srcs[t];
    size_t base = offarr[t] + i;
    float4 v = *(const float4*)(src + i);
    __nv_bfloat16 h0, h1, h2, h3, l0, l1, l2, l3;
    split1(v.x, h0, l0); split1(v.y, h1, l1);
    split1(v.z, h2, l2); split1(v.w, h3, l3);
    __nv_bfloat162 p;
    p.x = h0; p.y = h1; *(__nv_bfloat162*)(hi + base) = p;
    p.x = h2; p.y = h3; *(__nv_bfloat162*)(hi + base + 2) = p;
    p.x = l0; p.y = l1; *(__nv_bfloat162*)(lo + base) = p;
    p.x = l2; p.y = l3; *(__nv_bfloat162*)(lo + base + 2) = p;
}

// ---------------------------------------------------------------------------
// HMMA bf16x3 GEMM: C = A@W^T (+A2@W2^T) + bias. 128x128 tile, BK=32,
// 3-stage cp.async pipeline, swizzled smem, 2 CTAs/SM.
// OUTMODE: 0 = fp32, 1 = bf16 hi/lo pair, 2 = fp16
// ---------------------------------------------------------------------------
#define PART_SZ 8192u                // 128 rows * 64B
#define STAGE_SZ 32768u              // 4 parts
#define SMEM_BYTES (3u * STAGE_SZ)   // 98304

template <bool DUAL, bool RELU, int OUTMODE>
__global__ __launch_bounds__(256, 2)
void gemm_mma(const __nv_bfloat16* __restrict__ Ahi, const __nv_bfloat16* __restrict__ Alo,
              const __nv_bfloat16* __restrict__ Whi, const __nv_bfloat16* __restrict__ Wlo,
              const __nv_bfloat16* __restrict__ A2hi, const __nv_bfloat16* __restrict__ A2lo,
              const __nv_bfloat16* __restrict__ W2hi, const __nv_bfloat16* __restrict__ W2lo,
              const float* __restrict__ bias, const float* __restrict__ bias2,
              float* __restrict__ C,
              __nv_bfloat16* __restrict__ Chi, __nv_bfloat16* __restrict__ Clo,
              __half* __restrict__ Ch,
              int M, int Nout, int K)
{
    extern __shared__ char smem[];
    const uint32_t sbase = smem_u32(smem);
    const int tid = threadIdx.x;
    const int wid = tid >> 5;
    const int lane = tid & 31;
    const int bm = blockIdx.y * 128;
    const int bn = blockIdx.x * 128;
    const int wm = (wid & 1) * 64;
    const int wn = (wid >> 1) * 32;

    const int kcPer = K >> 5;
    const int nchunk = DUAL ? kcPer * 2 : kcPer;

    float acc[4][4][4];
#pragma unroll
    for (int a = 0; a < 4; ++a)
#pragma unroll
        for (int b = 0; b < 4; ++b)
#pragma unroll
            for (int c = 0; c < 4; ++c) acc[a][b][c] = 0.f;

    auto loadChunk = [&](int c) {
        const uint32_t stage = sbase + (uint32_t)(c % 3) * STAGE_SZ;
        const bool pair = DUAL && (c >= kcPer);
        const int kc = pair ? c - kcPer : c;
        const __nv_bfloat16* srcs[4] = {
            pair ? A2hi : Ahi, pair ? A2lo : Alo,
            pair ? W2hi : Whi, pair ? W2lo : Wlo };
#pragma unroll
        for (int p = 0; p < 4; ++p) {
            const __nv_bfloat16* src = srcs[p];
            const int rbase = (p < 2) ? bm : bn;
            const uint32_t pdst = stage + p * PART_SZ;
#pragma unroll
            for (int it = 0; it < 2; ++it) {
                int i = tid + it * 256;
                int row = i >> 2, ch = i & 3;
                cpa16(pdst + swzoff(row, ch),
                      src + (size_t)(rbase + row) * K + kc * 32 + ch * 8);
            }
        }
        CP_COMMIT();
    };

    auto computeChunk = [&](int s) {
        const uint32_t stage = sbase + (uint32_t)s * STAGE_SZ;
#pragma unroll
        for (int ks = 0; ks < 2; ++ks) {
            const int ch = ks * 2 + (lane >> 4);
            uint32_t ah[4][4], al[4][4], bh[2][4], bl[2][4];
#pragma unroll
            for (int mt = 0; mt < 4; ++mt) {
                const uint32_t off = swzoff(wm + mt * 16 + (lane & 15), ch);
                LDSM4(ah[mt], stage + off);
                LDSM4(al[mt], stage + PART_SZ + off);
            }
#pragma unroll
            for (int np = 0; np < 2; ++np) {
                const uint32_t off = swzoff(wn + np * 16 + (lane & 15), ch);
                LDSM4(bh[np], stage + 2 * PART_SZ + off);
                LDSM4(bl[np], stage + 3 * PART_SZ + off);
            }
#pragma unroll
            for (int mt = 0; mt < 4; ++mt) {
#pragma unroll
                for (int nt = 0; nt < 4; ++nt) {
                    const int np = nt >> 1;
                    const int o0 = (nt & 1);
                    const int o1 = o0 + 2;
                    MMA_BF16(acc[mt][nt], ah[mt], bh[np][o0], bh[np][o1]);
                    MMA_BF16(acc[mt][nt], ah[mt], bl[np][o0], bl[np][o1]);
                    MMA_BF16(acc[mt][nt], al[mt], bh[np][o0], bh[np][o1]);
                }
            }
        }
    };

    // 3-stage pipeline
    loadChunk(0);
    loadChunk(1);
    for (int c = 0; c < nchunk; ++c) {
        if (c + 1 < nchunk) { CP_WAIT(1); } else { CP_WAIT(0); }
        __syncthreads();
        if (c + 2 < nchunk) loadChunk(c + 2);
        computeChunk(c % 3);
    }

    // epilogue
    float bcol[4][2];
#pragma unroll
    for (int nt = 0; nt < 4; ++nt) {
        int col = bn + wn + nt * 8 + (lane & 3) * 2;
        float b0 = bias[col], b1 = bias[col + 1];
        if (DUAL) { b0 += bias2[col]; b1 += bias2[col + 1]; }
        bcol[nt][0] = b0; bcol[nt][1] = b1;
    }
#pragma unroll
    for (int mt = 0; mt < 4; ++mt) {
        int row0 = bm + wm + mt * 16 + (lane >> 2);
#pragma unroll
        for (int nt = 0; nt < 4; ++nt) {
            int col = bn + wn + nt * 8 + (lane & 3) * 2;
#pragma unroll
            for (int half = 0; half < 2; ++half) {
                int row = row0 + half * 8;
                float v0 = acc[mt][nt][half * 2 + 0] + bcol[nt][0];
                float v1 = acc[mt][nt][half * 2 + 1] + bcol[nt][1];
                if (RELU) { v0 = fmaxf(v0, 0.f); v1 = fmaxf(v1, 0.f); }
                size_t go = (size_t)row * Nout + col;
                if (OUTMODE == 1) {
                    __nv_bfloat16 h0, h1, l0, l1;
                    split1(v0, h0, l0); split1(v1, h1, l1);
                    __nv_bfloat162 p;
                    p.x = h0; p.y = h1; *(__nv_bfloat162*)(Chi + go) = p;
                    p.x = l0; p.y = l1; *(__nv_bfloat162*)(Clo + go) = p;
                } else if (OUTMODE == 2) {
                    __half2 p;
                    p.x = __float2half_rn(v0);
                    p.y = __float2half_rn(v1);
                    *(__half2*)(Ch + go) = p;
                } else {
                    *(float2*)(C + go) = make_float2(v0, v1);
                }
            }
        }
    }
}

// ---------------------------------------------------------------------------
// Local attention: one warp per query; k/v gathered as fp16; writes hi/lo bf16.
// ---------------------------------------------------------------------------
__global__ __launch_bounds__(256)
void attn_kernel(const float* __restrict__ q, const __half* __restrict__ k,
                 const __half* __restrict__ v, const int* __restrict__ kbc,
                 const int* __restrict__ ipair, const int* __restrict__ ibatch,
                 __nv_bfloat16* __restrict__ ohi, __nv_bfloat16* __restrict__ olo)
{
    __shared__ int sg[8][32];
    const int warp = threadIdx.x >> 5;
    const int lane = threadIdx.x & 31;
    const int n = blockIdx.x * 8 + warp;
    const int h = lane >> 2;
    const int s = lane & 3;
    const int doff = h * 32 + s * 8;

    int b = ibatch[n];
    int off = 0;
    for (int i = 0; i < b; ++i) off += kbc[i];

    int idx = ipair[n * 32 + lane];
    unsigned mb = __ballot_sync(0xffffffffu, idx < 0);
    sg[warp][lane] = ((idx < 0) ? 0 : idx) + off;
    __syncwarp();

    const float scale = 0.17677669529663687f;
    float qr[8];
    {
        float4 q0 = *(const float4*)&q[(size_t)n * 256 + doff];
        float4 q1 = *(const float4*)&q[(size_t)n * 256 + doff + 4];
        qr[0] = q0.x * scale; qr[1] = q0.y * scale; qr[2] = q0.z * scale; qr[3] = q0.w * scale;
        qr[4] = q1.x * scale; qr[5] = q1.y * scale; qr[6] = q1.z * scale; qr[7] = q1.w * scale;
    }

    float lg[32];
#pragma unroll
    for (int j = 0; j < 32; ++j) {
        const __half2* kr = (const __half2*)&k[(size_t)sg[warp][j] * 256 + doff];
        uint2 raw0 = *(const uint2*)kr;
        uint2 raw1 = *(const uint2*)(kr + 2);
        float2 a0 = __half22float2(*(__half2*)&raw0.x);
        float2 a1 = __half22float2(*(__half2*)&raw0.y);
        float2 a2 = __half22float2(*(__half2*)&raw1.x);
        float2 a3 = __half22float2(*(__half2*)&raw1.y);
        float t = qr[0] * a0.x + qr[1] * a0.y + qr[2] * a1.x + qr[3] * a1.y
                + qr[4] * a2.x + qr[5] * a2.y + qr[6] * a3.x + qr[7] * a3.y;
        t += __shfl_xor_sync(0xffffffffu, t, 1);
        t += __shfl_xor_sync(0xffffffffu, t, 2);
        lg[j] = ((mb >> j) & 1u) ? -1e9f : t;
    }

    float m = lg[0];
#pragma unroll
    for (int j = 1; j < 32; ++j) m = fmaxf(m, lg[j]);
    float sum = 0.f;
#pragma unroll
    for (int j = 0; j < 32; ++j) { lg[j] = __expf(lg[j] - m); sum += lg[j]; }
    float rinv = 1.f / sum;

    float acc[8];
#pragma unroll
    for (int i = 0; i < 8; ++i) acc[i] = 0.f;
#pragma unroll
    for (int j = 0; j < 32; ++j) {
        const __half2* vr = (const __half2*)&v[(size_t)sg[warp][j] * 256 + doff];
        uint2 raw0 = *(const uint2*)vr;
        uint2 raw1 = *(const uint2*)(vr + 2);
        float2 a0 = __half22float2(*(__half2*)&raw0.x);
        float2 a1 = __half22float2(*(__half2*)&raw0.y);
        float2 a2 = __half22float2(*(__half2*)&raw1.x);
        float2 a3 = __half22float2(*(__half2*)&raw1.y);
        float p = lg[j] * rinv;
        acc[0] += p * a0.x; acc[1] += p * a0.y; acc[2] += p * a1.x; acc[3] += p * a1.y;
        acc[4] += p * a2.x; acc[5] += p * a2.y; acc[6] += p * a3.x; acc[7] += p * a3.y;
    }

    size_t o = (size_t)n * 256 + doff;
#pragma unroll
    for (int i = 0; i < 8; i += 2) {
        __nv_bfloat16 h0, h1, l0, l1;
        split1(acc[i], h0, l0);
        split1(acc[i + 1], h1, l1);
        __nv_bfloat162 p;
        p.x = h0; p.y = h1; *(__nv_bfloat162*)(ohi + o + i) = p;
        p.x = l0; p.y = l1; *(__nv_bfloat162*)(olo + o + i) = p;
    }
}

// ---------------------------------------------------------------------------
// out = LayerNorm(a + b); optionally also writes hi/lo bf16 copy.
// ---------------------------------------------------------------------------
template <bool OUTBF>
__global__ __launch_bounds__(256)
void residual_ln(const float* __restrict__ a, const float* __restrict__ bsrc,
                 const float* __restrict__ g, const float* __restrict__ be,
                 float* __restrict__ out,
                 __nv_bfloat16* __restrict__ ohi, __nv_bfloat16* __restrict__ olo)
{
    const int warp = threadIdx.x >> 5;
    const int lane = threadIdx.x & 31;
    const int n = blockIdx.x * 8 + warp;
    const int base = lane * 8;

    float x[8];
    {
        const float4* pa0 = (const float4*)&a[(size_t)n * 256 + base];
        const float4* pb0 = (const float4*)&bsrc[(size_t)n * 256 + base];
        float4 a0 = pa0[0], a1 = pa0[1];
        float4 b0 = pb0[0], b1 = pb0[1];
        x[0] = a0.x + b0.x; x[1] = a0.y + b0.y; x[2] = a0.z + b0.z; x[3] = a0.w + b0.w;
        x[4] = a1.x + b1.x; x[5] = a1.y + b1.y; x[6] = a1.z + b1.z; x[7] = a1.w + b1.w;
    }
    float s = 0.f;
#pragma unroll
    for (int i = 0; i < 8; ++i) s += x[i];
#pragma unroll
    for (int o = 16; o > 0; o >>= 1) s += __shfl_xor_sync(0xffffffffu, s, o);
    float mean = s * (1.f / 256.f);

    float vs = 0.f;
#pragma unroll
    for (int i = 0; i < 8; ++i) { float d = x[i] - mean; vs += d * d; }
#pragma unroll
    for (int o = 16; o > 0; o >>= 1) vs += __shfl_xor_sync(0xffffffffu, vs, o);
    float inv = rsqrtf(vs * (1.f / 256.f) + LN_EPS);

    float4 gg0 = *(const float4*)&g[base];
    float4 gg1 = *(const float4*)&g[base + 4];
    float4 bb0 = *(const float4*)&be[base];
    float4 bb1 = *(const float4*)&be[base + 4];

    float r[8];
    r[0] = (x[0] - mean) * inv * gg0.x + bb0.x;
    r[1] = (x[1] - mean) * inv * gg0.y + bb0.y;
    r[2] = (x[2] - mean) * inv * gg0.z + bb0.z;
    r[3] = (x[3] - mean) * inv * gg0.w + bb0.w;
    r[4] = (x[4] - mean) * inv * gg1.x + bb1.x;
    r[5] = (x[5] - mean) * inv * gg1.y + bb1.y;
    r[6] = (x[6] - mean) * inv * gg1.z + bb1.z;
    r[7] = (x[7] - mean) * inv * gg1.w + bb1.w;

    size_t o = (size_t)n * 256 + base;
    *(float4*)(out + o) = make_float4(r[0], r[1], r[2], r[3]);
    *(float4*)(out + o + 4) = make_float4(r[4], r[5], r[6], r[7]);

    if (OUTBF) {
#pragma unroll
        for (int i = 0; i < 8; i += 2) {
            __nv_bfloat16 h0, h1, l0, l1;
            split1(r[i], h0, l0);
            split1(r[i + 1], h1, l1);
            __nv_bfloat162 p;
            p.x = h0; p.y = h1; *(__nv_bfloat162*)(ohi + o + i) = p;
            p.x = l0; p.y = l1; *(__nv_bfloat162*)(olo + o + i) = p;
        }
    }
}

// ---------------------------------------------------------------------------
extern "C" void kernel_launch(void* const* d_in, const int* in_sizes, int n_in,
                              void* d_out, int out_size)
{
    const float* tgt  = (const float*)d_in[0];
    const float* mem  = (const float*)d_in[1];
    const float* pos  = (const float*)d_in[2];
    const int*   kbc  = (const int*)d_in[3];
    const int*   ipair  = (const int*)d_in[4];
    const int*   ibatch = (const int*)d_in[5];
    const float* Wq  = (const float*)d_in[6];
    const float* bq  = (const float*)d_in[7];
    const float* Wkc = (const float*)d_in[8];
    const float* bkc = (const float*)d_in[9];
    const float* Wkp = (const float*)d_in[10];
    const float* bkp = (const float*)d_in[11];
    const float* Wv  = (const float*)d_in[12];
    const float* bv  = (const float*)d_in[13];
    const float* Wo  = (const float*)d_in[14];
    const float* bo  = (const float*)d_in[15];
    const float* W1  = (const float*)d_in[16];
    const float* b1  = (const float*)d_in[17];
    const float* W2  = (const float*)d_in[18];
    const float* b2  = (const float*)d_in[19];
    const float* g2  = (const float*)d_in[20];
    const float* be2 = (const float*)d_in[21];
    const float* g3  = (const float*)d_in[22];
    const float* be3 = (const float*)d_in[23];
    float* out = (float*)d_out;

    float* f32 = nullptr;
    __half* hp = nullptr;
    __nv_bfloat16* hi = nullptr;
    __nv_bfloat16* lo = nullptr;
    cudaGetSymbolAddress((void**)&f32, g_f32);
    cudaGetSymbolAddress((void**)&hp, g_half);
    cudaGetSymbolAddress((void**)&hi, g_hi);
    cudaGetSymbolAddress((void**)&lo, g_lo);

    float* q_  = f32 + 0u * NQ * DM;
    float* t2_ = f32 + 1u * NQ * DM;
    float* x_  = f32 + 2u * NQ * DM;
    __half* k_ = hp + 0u * NQ * DM;
    __half* v_ = hp + 1u * NQ * DM;

    cudaFuncSetAttribute(gemm_mma<false, false, 0>,
                         cudaFuncAttributeMaxDynamicSharedMemorySize, SMEM_BYTES);
    cudaFuncSetAttribute(gemm_mma<true, false, 2>,
                         cudaFuncAttributeMaxDynamicSharedMemorySize, SMEM_BYTES);
    cudaFuncSetAttribute(gemm_mma<false, false, 2>,
                         cudaFuncAttributeMaxDynamicSharedMemorySize, SMEM_BYTES);
    cudaFuncSetAttribute(gemm_mma<false, true, 1>,
                         cudaFuncAttributeMaxDynamicSharedMemorySize, SMEM_BYTES);

    // converts
    conv_all<<<dim3(4096, 10), 256>>>(tgt, mem, pos, Wq, Wkc, Wkp, Wv, Wo, W1, W2, hi, lo);

    dim3 blk(256);
    dim3 gP(2, 128);    // Nout=256
    dim3 gF1(8, 128);   // Nout=1024

    // q = tgt @ Wq^T + bq  (fp32 out)
    gemm_mma<false, false, 0><<<gP, blk, SMEM_BYTES>>>(
        hi + OFF_TGT, lo + OFF_TGT, hi + OFF_WQ, lo + OFF_WQ,
        nullptr, nullptr, nullptr, nullptr, bq, nullptr,
        q_, nullptr, nullptr, nullptr, NQ, DM, DM);
    // k = mem @ Wkc^T + pos @ Wkp^T + biases  (fp16 out)
    gemm_mma<true, false, 2><<<gP, blk, SMEM_BYTES>>>(
        hi + OFF_MEM, lo + OFF_MEM, hi + OFF_WKC, lo + OFF_WKC,
        hi + OFF_POS, lo + OFF_POS, hi + OFF_WKP, lo + OFF_WKP, bkc, bkp,
        nullptr, nullptr, nullptr, k_, NQ, DM, DM);
    // v = mem @ Wv^T + bv  (fp16 out)
    gemm_mma<false, false, 2><<<gP, blk, SMEM_BYTES>>>(
        hi + OFF_MEM, lo + OFF_MEM, hi + OFF_WV, lo + OFF_WV,
        nullptr, nullptr, nullptr, nullptr, bv, nullptr,
        nullptr, nullptr, nullptr, v_, NQ, DM, DM);
    // attention -> at (hi/lo)
    attn_kernel<<<NQ / 8, blk>>>(q_, k_, v_, kbc, ipair, ibatch, hi + OFF_AT, lo + OFF_AT);
    // t2 = at @ Wo^T + bo
    gemm_mma<false, false, 0><<<gP, blk, SMEM_BYTES>>>(
        hi + OFF_AT, lo + OFF_AT, hi + OFF_WO, lo + OFF_WO,
        nullptr, nullptr, nullptr, nullptr, bo, nullptr,
        t2_, nullptr, nullptr, nullptr, NQ, DM, DM);
    // x = LN(tgt + t2), also hi/lo
    residual_ln<true><<<NQ / 8, blk>>>(tgt, t2_, g2, be2, x_, hi + OFF_X, lo + OFF_X);
    // h = relu(x @ W1^T + b1) -> hi/lo only
    gemm_mma<false, true, 1><<<gF1, blk, SMEM_BYTES>>>(
        hi + OFF_X, lo + OFF_X, hi + OFF_W1, lo + OFF_W1,
        nullptr, nullptr, nullptr, nullptr, b1, nullptr,
        nullptr, hi + OFF_H, lo + OFF_H, nullptr, NQ, DFF_, DM);
    // y = h @ W2^T + b2
    gemm_mma<false, false, 0><<<gP, blk, SMEM_BYTES>>>(
        hi + OFF_H, lo + OFF_H, hi + OFF_W2, lo + OFF_W2,
        nullptr, nullptr, nullptr, nullptr, b2, nullptr,
        t2_, nullptr, nullptr, nullptr, NQ, DM, DFF_);
    // out = LN(x + y)
    residual_ln<false><<<NQ / 8, blk>>>(x_, t2_, g3, be3, out, nullptr, nullptr);
}

// round 5
// speedup vs baseline: 2.9436x; 1.9877x over previous
#include <cuda_runtime.h>
#include <cuda_fp16.h>
#include <cstdint>

#define NQ 16384
#define DM 256
#define DFF_ 1024
#define LN_EPS 1e-5f

// ---------------------------------------------------------------------------
// scratch
// ---------------------------------------------------------------------------
// fp32: t2, x
__device__ float g_f32[2u * NQ * DM];
// fp16 q,k,v
__device__ __half g_qkv[3u * NQ * DM];

// fp16 pool (element offsets)
#define OFF_TGT 0u
#define OFF_MEM 4194304u
#define OFF_POS 8388608u
#define OFF_AT  12582912u
#define OFF_X   16777216u
#define OFF_H   20971520u
#define OFF_WQ  37748736u
#define OFF_WKC 37814272u
#define OFF_WKP 37879808u
#define OFF_WV  37945344u
#define OFF_WO  38010880u
#define OFF_W1  38076416u
#define OFF_W2  38338560u
#define TOT_H16 38600704u
__device__ __half g_h16[TOT_H16];

// ---------------------------------------------------------------------------
// helpers
// ---------------------------------------------------------------------------
__device__ __forceinline__ uint32_t smem_u32(const void* p) {
    uint32_t a;
    asm("{ .reg .u64 t; cvta.to.shared.u64 t, %1; cvt.u32.u64 %0, t; }"
        : "=r"(a) : "l"(p));
    return a;
}
__device__ __forceinline__ void cpa16(uint32_t dst, const void* src) {
    asm volatile("cp.async.cg.shared.global [%0], [%1], 16;"
                 :: "r"(dst), "l"(src) : "memory");
}
#define CP_COMMIT() asm volatile("cp.async.commit_group;" ::: "memory")
#define CP_WAIT(n)  asm volatile("cp.async.wait_group %0;" :: "n"(n) : "memory")

#define LDSM4(r, addr) \
    asm volatile("ldmatrix.sync.aligned.m8n8.x4.shared.b16 {%0,%1,%2,%3}, [%4];" \
        : "=r"((r)[0]), "=r"((r)[1]), "=r"((r)[2]), "=r"((r)[3]) : "r"(addr))

#define MMA_F16(d, a, b0, b1) \
    asm volatile("mma.sync.aligned.m16n8k16.row.col.f32.f16.f16.f32 " \
        "{%0,%1,%2,%3}, {%4,%5,%6,%7}, {%8,%9}, {%0,%1,%2,%3};" \
        : "+f"((d)[0]), "+f"((d)[1]), "+f"((d)[2]), "+f"((d)[3]) \
        : "r"((a)[0]), "r"((a)[1]), "r"((a)[2]), "r"((a)[3]), "r"(b0), "r"(b1))

// swizzled smem byte offset for (row, chunk16B) with 64B rows (BK=32 fp16)
__device__ __forceinline__ uint32_t swzoff(int row, int ch) {
    return (uint32_t)(row * 64 + ((ch ^ ((row >> 1) & 3)) << 4));
}

__device__ __forceinline__ uint32_t pack2(float a, float b) {
    __half2 p;
    p.x = __float2half_rn(a);
    p.y = __float2half_rn(b);
    return *(uint32_t*)&p;
}

// ---------------------------------------------------------------------------
// Conversion: fp32 -> fp16, 10 tensors via blockIdx.y, 8 elems/thread
// ---------------------------------------------------------------------------
__global__ __launch_bounds__(256)
void conv_all(const float* s0, const float* s1, const float* s2, const float* s3,
              const float* s4, const float* s5, const float* s6, const float* s7,
              const float* s8, const float* s9, __half* dst)
{
    const int t = blockIdx.y;
    const unsigned narr[10] = {4194304u, 4194304u, 4194304u, 65536u, 65536u,
                               65536u, 65536u, 65536u, 262144u, 262144u};
    const unsigned offarr[10] = {OFF_TGT, OFF_MEM, OFF_POS, OFF_WQ, OFF_WKC,
                                 OFF_WKP, OFF_WV, OFF_WO, OFF_W1, OFF_W2};
    const float* srcs[10] = {s0, s1, s2, s3, s4, s5, s6, s7, s8, s9};
    unsigned i = (blockIdx.x * 256u + threadIdx.x) * 8u;
    if (i >= narr[t]) return;
    const float* src = srcs[t];
    float4 v0 = *(const float4*)(src + i);
    float4 v1 = *(const float4*)(src + i + 4);
    uint4 o;
    o.x = pack2(v0.x, v0.y);
    o.y = pack2(v0.z, v0.w);
    o.z = pack2(v1.x, v1.y);
    o.w = pack2(v1.z, v1.w);
    *(uint4*)(dst + offarr[t] + i) = o;
}

// ---------------------------------------------------------------------------
// HMMA fp16 GEMM: C = A@W^T (+A2@W2^T) + bias. 128x128 tile, BK=32,
// 3-stage cp.async pipeline, swizzled smem.
// OUTMODE: 0 = fp32, 1 = fp16
// ---------------------------------------------------------------------------
#define PART_SZ 8192u                // 128 rows * 64B
#define STAGE_SZ 16384u              // A + W
#define SMEM_BYTES (3u * STAGE_SZ)   // 49152

template <bool DUAL, bool RELU, int OUTMODE>
__global__ __launch_bounds__(256, 2)
void gemm_mma(const __half* __restrict__ A, const __half* __restrict__ W,
              const __half* __restrict__ A2, const __half* __restrict__ W2,
              const float* __restrict__ bias, const float* __restrict__ bias2,
              float* __restrict__ C, __half* __restrict__ Ch,
              int M, int Nout, int K)
{
    extern __shared__ char smem[];
    const uint32_t sbase = smem_u32(smem);
    const int tid = threadIdx.x;
    const int wid = tid >> 5;
    const int lane = tid & 31;
    const int bm = blockIdx.y * 128;
    const int bn = blockIdx.x * 128;
    const int wm = (wid & 1) * 64;
    const int wn = (wid >> 1) * 32;

    const int kcPer = K >> 5;
    const int nchunk = DUAL ? kcPer * 2 : kcPer;

    float acc[4][4][4];
#pragma unroll
    for (int a = 0; a < 4; ++a)
#pragma unroll
        for (int b = 0; b < 4; ++b)
#pragma unroll
            for (int c = 0; c < 4; ++c) acc[a][b][c] = 0.f;

    auto loadChunk = [&](int c) {
        const uint32_t stage = sbase + (uint32_t)(c % 3) * STAGE_SZ;
        const bool pair = DUAL && (c >= kcPer);
        const int kc = pair ? c - kcPer : c;
        const __half* srcA = pair ? A2 : A;
        const __half* srcW = pair ? W2 : W;
#pragma unroll
        for (int it = 0; it < 2; ++it) {
            int i = tid + it * 256;
            int row = i >> 2, ch = i & 3;
            cpa16(stage + swzoff(row, ch),
                  srcA + (size_t)(bm + row) * K + kc * 32 + ch * 8);
            cpa16(stage + PART_SZ + swzoff(row, ch),
                  srcW + (size_t)(bn + row) * K + kc * 32 + ch * 8);
        }
        CP_COMMIT();
    };

    auto computeChunk = [&](int s) {
        const uint32_t stage = sbase + (uint32_t)s * STAGE_SZ;
#pragma unroll
        for (int ks = 0; ks < 2; ++ks) {
            const int ch = ks * 2 + (lane >> 4);
            uint32_t af[4][4], bf[2][4];
#pragma unroll
            for (int mt = 0; mt < 4; ++mt)
                LDSM4(af[mt], stage + swzoff(wm + mt * 16 + (lane & 15), ch));
#pragma unroll
            for (int np = 0; np < 2; ++np)
                LDSM4(bf[np], stage + PART_SZ + swzoff(wn + np * 16 + (lane & 15), ch));
#pragma unroll
            for (int mt = 0; mt < 4; ++mt) {
#pragma unroll
                for (int nt = 0; nt < 4; ++nt) {
                    const int np = nt >> 1;
                    const int o0 = (nt & 1);
                    MMA_F16(acc[mt][nt], af[mt], bf[np][o0], bf[np][o0 + 2]);
                }
            }
        }
    };

    // 3-stage pipeline
    loadChunk(0);
    loadChunk(1);
    for (int c = 0; c < nchunk; ++c) {
        if (c + 1 < nchunk) { CP_WAIT(1); } else { CP_WAIT(0); }
        __syncthreads();
        if (c + 2 < nchunk) loadChunk(c + 2);
        computeChunk(c % 3);
    }

    // epilogue
    float bcol[4][2];
#pragma unroll
    for (int nt = 0; nt < 4; ++nt) {
        int col = bn + wn + nt * 8 + (lane & 3) * 2;
        float b0 = bias[col], b1 = bias[col + 1];
        if (DUAL) { b0 += bias2[col]; b1 += bias2[col + 1]; }
        bcol[nt][0] = b0; bcol[nt][1] = b1;
    }
#pragma unroll
    for (int mt = 0; mt < 4; ++mt) {
        int row0 = bm + wm + mt * 16 + (lane >> 2);
#pragma unroll
        for (int nt = 0; nt < 4; ++nt) {
            int col = bn + wn + nt * 8 + (lane & 3) * 2;
#pragma unroll
            for (int half = 0; half < 2; ++half) {
                int row = row0 + half * 8;
                float v0 = acc[mt][nt][half * 2 + 0] + bcol[nt][0];
                float v1 = acc[mt][nt][half * 2 + 1] + bcol[nt][1];
                if (RELU) { v0 = fmaxf(v0, 0.f); v1 = fmaxf(v1, 0.f); }
                size_t go = (size_t)row * Nout + col;
                if (OUTMODE == 1) {
                    *(uint32_t*)(Ch + go) = pack2(v0, v1);
                } else {
                    *(float2*)(C + go) = make_float2(v0, v1);
                }
            }
        }
    }
}

// ---------------------------------------------------------------------------
// Local attention: one warp per query; q/k/v fp16, output fp16.
// ---------------------------------------------------------------------------
__global__ __launch_bounds__(256, 2)
void attn_kernel(const __half* __restrict__ q, const __half* __restrict__ k,
                 const __half* __restrict__ v, const int* __restrict__ kbc,
                 const int* __restrict__ ipair, const int* __restrict__ ibatch,
                 __half* __restrict__ oat)
{
    __shared__ int sg[8][32];
    const int warp = threadIdx.x >> 5;
    const int lane = threadIdx.x & 31;
    const int n = blockIdx.x * 8 + warp;
    const int h = lane >> 2;
    const int s = lane & 3;
    const int doff = h * 32 + s * 8;

    int b = ibatch[n];
    int off = 0;
    for (int i = 0; i < b; ++i) off += kbc[i];

    int idx = ipair[n * 32 + lane];
    unsigned mb = __ballot_sync(0xffffffffu, idx < 0);
    sg[warp][lane] = ((idx < 0) ? 0 : idx) + off;
    __syncwarp();

    const float scale = 0.17677669529663687f;
    float qr[8];
    {
        uint4 raw = *(const uint4*)&q[(size_t)n * 256 + doff];
        float2 a0 = __half22float2(*(__half2*)&raw.x);
        float2 a1 = __half22float2(*(__half2*)&raw.y);
        float2 a2 = __half22float2(*(__half2*)&raw.z);
        float2 a3 = __half22float2(*(__half2*)&raw.w);
        qr[0] = a0.x * scale; qr[1] = a0.y * scale;
        qr[2] = a1.x * scale; qr[3] = a1.y * scale;
        qr[4] = a2.x * scale; qr[5] = a2.y * scale;
        qr[6] = a3.x * scale; qr[7] = a3.y * scale;
    }

    float lg[32];
#pragma unroll
    for (int j = 0; j < 32; ++j) {
        uint4 raw = *(const uint4*)&k[(size_t)sg[warp][j] * 256 + doff];
        float2 a0 = __half22float2(*(__half2*)&raw.x);
        float2 a1 = __half22float2(*(__half2*)&raw.y);
        float2 a2 = __half22float2(*(__half2*)&raw.z);
        float2 a3 = __half22float2(*(__half2*)&raw.w);
        float t = qr[0] * a0.x + qr[1] * a0.y + qr[2] * a1.x + qr[3] * a1.y
                + qr[4] * a2.x + qr[5] * a2.y + qr[6] * a3.x + qr[7] * a3.y;
        t += __shfl_xor_sync(0xffffffffu, t, 1);
        t += __shfl_xor_sync(0xffffffffu, t, 2);
        lg[j] = ((mb >> j) & 1u) ? -1e9f : t;
    }

    float m = lg[0];
#pragma unroll
    for (int j = 1; j < 32; ++j) m = fmaxf(m, lg[j]);
    float sum = 0.f;
#pragma unroll
    for (int j = 0; j < 32; ++j) { lg[j] = __expf(lg[j] - m); sum += lg[j]; }
    float rinv = 1.f / sum;

    float acc[8];
#pragma unroll
    for (int i = 0; i < 8; ++i) acc[i] = 0.f;
#pragma unroll
    for (int j = 0; j < 32; ++j) {
        uint4 raw = *(const uint4*)&v[(size_t)sg[warp][j] * 256 + doff];
        float2 a0 = __half22float2(*(__half2*)&raw.x);
        float2 a1 = __half22float2(*(__half2*)&raw.y);
        float2 a2 = __half22float2(*(__half2*)&raw.z);
        float2 a3 = __half22float2(*(__half2*)&raw.w);
        float p = lg[j] * rinv;
        acc[0] += p * a0.x; acc[1] += p * a0.y; acc[2] += p * a1.x; acc[3] += p * a1.y;
        acc[4] += p * a2.x; acc[5] += p * a2.y; acc[6] += p * a3.x; acc[7] += p * a3.y;
    }

    uint4 o;
    o.x = pack2(acc[0], acc[1]);
    o.y = pack2(acc[2], acc[3]);
    o.z = pack2(acc[4], acc[5]);
    o.w = pack2(acc[6], acc[7]);
    *(uint4*)(oat + (size_t)n * 256 + doff) = o;
}

// ---------------------------------------------------------------------------
// out = LayerNorm(a + b); optionally also writes fp16 copy.
// ---------------------------------------------------------------------------
template <bool OUTH>
__global__ __launch_bounds__(256)
void residual_ln(const float* __restrict__ a, const float* __restrict__ bsrc,
                 const float* __restrict__ g, const float* __restrict__ be,
                 float* __restrict__ out, __half* __restrict__ oh)
{
    const int warp = threadIdx.x >> 5;
    const int lane = threadIdx.x & 31;
    const int n = blockIdx.x * 8 + warp;
    const int base = lane * 8;

    float x[8];
    {
        const float4* pa0 = (const float4*)&a[(size_t)n * 256 + base];
        const float4* pb0 = (const float4*)&bsrc[(size_t)n * 256 + base];
        float4 a0 = pa0[0], a1 = pa0[1];
        float4 b0 = pb0[0], b1 = pb0[1];
        x[0] = a0.x + b0.x; x[1] = a0.y + b0.y; x[2] = a0.z + b0.z; x[3] = a0.w + b0.w;
        x[4] = a1.x + b1.x; x[5] = a1.y + b1.y; x[6] = a1.z + b1.z; x[7] = a1.w + b1.w;
    }
    float s = 0.f;
#pragma unroll
    for (int i = 0; i < 8; ++i) s += x[i];
#pragma unroll
    for (int o = 16; o > 0; o >>= 1) s += __shfl_xor_sync(0xffffffffu, s, o);
    float mean = s * (1.f / 256.f);

    float vs = 0.f;
#pragma unroll
    for (int i = 0; i < 8; ++i) { float d = x[i] - mean; vs += d * d; }
#pragma unroll
    for (int o = 16; o > 0; o >>= 1) vs += __shfl_xor_sync(0xffffffffu, vs, o);
    float inv = rsqrtf(vs * (1.f / 256.f) + LN_EPS);

    float4 gg0 = *(const float4*)&g[base];
    float4 gg1 = *(const float4*)&g[base + 4];
    float4 bb0 = *(const float4*)&be[base];
    float4 bb1 = *(const float4*)&be[base + 4];

    float r[8];
    r[0] = (x[0] - mean) * inv * gg0.x + bb0.x;
    r[1] = (x[1] - mean) * inv * gg0.y + bb0.y;
    r[2] = (x[2] - mean) * inv * gg0.z + bb0.z;
    r[3] = (x[3] - mean) * inv * gg0.w + bb0.w;
    r[4] = (x[4] - mean) * inv * gg1.x + bb1.x;
    r[5] = (x[5] - mean) * inv * gg1.y + bb1.y;
    r[6] = (x[6] - mean) * inv * gg1.z + bb1.z;
    r[7] = (x[7] - mean) * inv * gg1.w + bb1.w;

    size_t o = (size_t)n * 256 + base;
    *(float4*)(out + o) = make_float4(r[0], r[1], r[2], r[3]);
    *(float4*)(out + o + 4) = make_float4(r[4], r[5], r[6], r[7]);

    if (OUTH) {
        uint4 p;
        p.x = pack2(r[0], r[1]);
        p.y = pack2(r[2], r[3]);
        p.z = pack2(r[4], r[5]);
        p.w = pack2(r[6], r[7]);
        *(uint4*)(oh + o) = p;
    }
}

// ---------------------------------------------------------------------------
extern "C" void kernel_launch(void* const* d_in, const int* in_sizes, int n_in,
                              void* d_out, int out_size)
{
    const float* tgt  = (const float*)d_in[0];
    const float* mem  = (const float*)d_in[1];
    const float* pos  = (const float*)d_in[2];
    const int*   kbc  = (const int*)d_in[3];
    const int*   ipair  = (const int*)d_in[4];
    const int*   ibatch = (const int*)d_in[5];
    const float* Wq  = (const float*)d_in[6];
    const float* bq  = (const float*)d_in[7];
    const float* Wkc = (const float*)d_in[8];
    const float* bkc = (const float*)d_in[9];
    const float* Wkp = (const float*)d_in[10];
    const float* bkp = (const float*)d_in[11];
    const float* Wv  = (const float*)d_in[12];
    const float* bv  = (const float*)d_in[13];
    const float* Wo  = (const float*)d_in[14];
    const float* bo  = (const float*)d_in[15];
    const float* W1  = (const float*)d_in[16];
    const float* b1  = (const float*)d_in[17];
    const float* W2  = (const float*)d_in[18];
    const float* b2  = (const float*)d_in[19];
    const float* g2  = (const float*)d_in[20];
    const float* be2 = (const float*)d_in[21];
    const float* g3  = (const float*)d_in[22];
    const float* be3 = (const float*)d_in[23];
    float* out = (float*)d_out;

    float* f32 = nullptr;
    __half* qkv = nullptr;
    __half* h16 = nullptr;
    cudaGetSymbolAddress((void**)&f32, g_f32);
    cudaGetSymbolAddress((void**)&qkv, g_qkv);
    cudaGetSymbolAddress((void**)&h16, g_h16);

    float* t2_ = f32 + 0u * NQ * DM;
    float* x_  = f32 + 1u * NQ * DM;
    __half* q_ = qkv + 0u * NQ * DM;
    __half* k_ = qkv + 1u * NQ * DM;
    __half* v_ = qkv + 2u * NQ * DM;

    cudaFuncSetAttribute(gemm_mma<false, false, 0>,
                         cudaFuncAttributeMaxDynamicSharedMemorySize, SMEM_BYTES);
    cudaFuncSetAttribute(gemm_mma<true, false, 1>,
                         cudaFuncAttributeMaxDynamicSharedMemorySize, SMEM_BYTES);
    cudaFuncSetAttribute(gemm_mma<false, false, 1>,
                         cudaFuncAttributeMaxDynamicSharedMemorySize, SMEM_BYTES);
    cudaFuncSetAttribute(gemm_mma<false, true, 1>,
                         cudaFuncAttributeMaxDynamicSharedMemorySize, SMEM_BYTES);

    // converts (fp32 -> fp16), 8 elems/thread
    conv_all<<<dim3(2048, 10), 256>>>(tgt, mem, pos, Wq, Wkc, Wkp, Wv, Wo, W1, W2, h16);

    dim3 blk(256);
    dim3 gP(2, 128);    // Nout=256
    dim3 gF1(8, 128);   // Nout=1024

    // q = tgt @ Wq^T + bq  (fp16 out)
    gemm_mma<false, false, 1><<<gP, blk, SMEM_BYTES>>>(
        h16 + OFF_TGT, h16 + OFF_WQ, nullptr, nullptr, bq, nullptr,
        nullptr, q_, NQ, DM, DM);
    // k = mem @ Wkc^T + pos @ Wkp^T + biases  (fp16 out)
    gemm_mma<true, false, 1><<<gP, blk, SMEM_BYTES>>>(
        h16 + OFF_MEM, h16 + OFF_WKC, h16 + OFF_POS, h16 + OFF_WKP, bkc, bkp,
        nullptr, k_, NQ, DM, DM);
    // v = mem @ Wv^T + bv  (fp16 out)
    gemm_mma<false, false, 1><<<gP, blk, SMEM_BYTES>>>(
        h16 + OFF_MEM, h16 + OFF_WV, nullptr, nullptr, bv, nullptr,
        nullptr, v_, NQ, DM, DM);
    // attention -> at (fp16)
    attn_kernel<<<NQ / 8, blk>>>(q_, k_, v_, kbc, ipair, ibatch, h16 + OFF_AT);
    // t2 = at @ Wo^T + bo  (fp32 out)
    gemm_mma<false, false, 0><<<gP, blk, SMEM_BYTES>>>(
        h16 + OFF_AT, h16 + OFF_WO, nullptr, nullptr, bo, nullptr,
        t2_, nullptr, NQ, DM, DM);
    // x = LN(tgt + t2), also fp16 copy
    residual_ln<true><<<NQ / 8, blk>>>(tgt, t2_, g2, be2, x_, h16 + OFF_X);
    // h = relu(x @ W1^T + b1)  (fp16 out)
    gemm_mma<false, true, 1><<<gF1, blk, SMEM_BYTES>>>(
        h16 + OFF_X, h16 + OFF_W1, nullptr, nullptr, b1, nullptr,
        nullptr, h16 + OFF_H, NQ, DFF_, DM);
    // y = h @ W2^T + b2  (fp32 out)
    gemm_mma<false, false, 0><<<gP, blk, SMEM_BYTES>>>(
        h16 + OFF_H, h16 + OFF_W2, nullptr, nullptr, b2, nullptr,
        t2_, nullptr, NQ, DM, DFF_);
    // out = LN(x + y)
    residual_ln<false><<<NQ / 8, blk>>>(x_, t2_, g3, be3, out, nullptr);
}

// round 6
// speedup vs baseline: 3.1663x; 1.0757x over previous
#include <cuda_runtime.h>
#include <cuda_fp16.h>
#include <cstdint>

#define NQ 16384
#define DM 256
#define DFF_ 1024
#define LN_EPS 1e-5f

// ---------------------------------------------------------------------------
// scratch
// ---------------------------------------------------------------------------
__device__ float g_f32[2u * NQ * DM];          // t2, x
__device__ __half g_qkv[3u * NQ * DM];         // q, k, v

// fp16 pool (element offsets)
#define OFF_TGT 0u
#define OFF_MEM 4194304u
#define OFF_POS 8388608u
#define OFF_AT  12582912u
#define OFF_X   16777216u
#define OFF_H   20971520u
#define OFF_WQ  37748736u
#define OFF_WKC 37814272u
#define OFF_WKP 37879808u
#define OFF_WV  37945344u
#define OFF_WO  38010880u
#define OFF_W1  38076416u
#define OFF_W2  38338560u
#define TOT_H16 38600704u
__device__ __half g_h16[TOT_H16];

// ---------------------------------------------------------------------------
// helpers
// ---------------------------------------------------------------------------
__device__ __forceinline__ uint32_t smem_u32(const void* p) {
    uint32_t a;
    asm("{ .reg .u64 t; cvta.to.shared.u64 t, %1; cvt.u32.u64 %0, t; }"
        : "=r"(a) : "l"(p));
    return a;
}
__device__ __forceinline__ void cpa16(uint32_t dst, const void* src) {
    asm volatile("cp.async.cg.shared.global [%0], [%1], 16;"
                 :: "r"(dst), "l"(src) : "memory");
}
#define CP_COMMIT() asm volatile("cp.async.commit_group;" ::: "memory")
#define CP_WAIT(n)  asm volatile("cp.async.wait_group %0;" :: "n"(n) : "memory")

#define LDSM4(r, addr) \
    asm volatile("ldmatrix.sync.aligned.m8n8.x4.shared.b16 {%0,%1,%2,%3}, [%4];" \
        : "=r"((r)[0]), "=r"((r)[1]), "=r"((r)[2]), "=r"((r)[3]) : "r"(addr))

#define MMA_F16(d, a, b0, b1) \
    asm volatile("mma.sync.aligned.m16n8k16.row.col.f32.f16.f16.f32 " \
        "{%0,%1,%2,%3}, {%4,%5,%6,%7}, {%8,%9}, {%0,%1,%2,%3};" \
        : "+f"((d)[0]), "+f"((d)[1]), "+f"((d)[2]), "+f"((d)[3]) \
        : "r"((a)[0]), "r"((a)[1]), "r"((a)[2]), "r"((a)[3]), "r"(b0), "r"(b1))

// swizzled smem byte offset for (row, chunk16B) with 64B rows (BK=32 fp16)
__device__ __forceinline__ uint32_t swzoff(int row, int ch) {
    return (uint32_t)(row * 64 + ((ch ^ ((row >> 1) & 3)) << 4));
}

__device__ __forceinline__ uint32_t pack2(float a, float b) {
    __half2 p;
    p.x = __float2half_rn(a);
    p.y = __float2half_rn(b);
    return *(uint32_t*)&p;
}

#define PART_SZ 8192u                // 128 rows * 64B
#define STAGE_SZ 16384u              // A + W
#define NSTAGE 4
#define SMEM_BYTES (NSTAGE * STAGE_SZ)   // 65536

// ---------------------------------------------------------------------------
// GEMM core: acc += A[bm:bm+128, :K] @ W[bn:bn+128, :K]^T, K = CHUNKS*32
// fully unrolled 4-stage cp.async pipeline.
// ---------------------------------------------------------------------------
template <int CHUNKS>
__device__ __forceinline__ void gemm_core(
    uint32_t sbase, const __half* __restrict__ A, const __half* __restrict__ W,
    int bm, int bn, int tid, int wm, int wn, int lane, float (&acc)[4][4][4])
{
    constexpr int K = CHUNKS * 32;
    __syncthreads();   // protect smem reuse from a previous pass

    auto load = [&](int c) {
        const uint32_t stage = sbase + (uint32_t)(c % NSTAGE) * STAGE_SZ;
#pragma unroll
        for (int it = 0; it < 2; ++it) {
            int i = tid + it * 256;
            int row = i >> 2, ch = i & 3;
            cpa16(stage + swzoff(row, ch),
                  A + (size_t)(bm + row) * K + c * 32 + ch * 8);
            cpa16(stage + PART_SZ + swzoff(row, ch),
                  W + (size_t)(bn + row) * K + c * 32 + ch * 8);
        }
        CP_COMMIT();
    };

    auto comp = [&](int s) {
        const uint32_t stage = sbase + (uint32_t)s * STAGE_SZ;
#pragma unroll
        for (int ks = 0; ks < 2; ++ks) {
            const int ch = ks * 2 + (lane >> 4);
            uint32_t af[4][4], bf[2][4];
#pragma unroll
            for (int mt = 0; mt < 4; ++mt)
                LDSM4(af[mt], stage + swzoff(wm + mt * 16 + (lane & 15), ch));
#pragma unroll
            for (int np = 0; np < 2; ++np)
                LDSM4(bf[np], stage + PART_SZ + swzoff(wn + np * 16 + (lane & 15), ch));
#pragma unroll
            for (int mt = 0; mt < 4; ++mt) {
#pragma unroll
                for (int nt = 0; nt < 4; ++nt) {
                    const int np = nt >> 1;
                    const int o0 = (nt & 1);
                    MMA_F16(acc[mt][nt], af[mt], bf[np][o0], bf[np][o0 + 2]);
                }
            }
        }
    };

#pragma unroll
    for (int c = 0; c < NSTAGE - 1; ++c) load(c);
#pragma unroll
    for (int c = 0; c < CHUNKS; ++c) {
        const int rem = CHUNKS - 1 - c;
        if (rem >= 2) { CP_WAIT(2); }
        else if (rem == 1) { CP_WAIT(1); }
        else { CP_WAIT(0); }
        __syncthreads();
        if (c + NSTAGE - 1 < CHUNKS) load(c + NSTAGE - 1);
        comp(c % NSTAGE);
    }
}

// epilogue: acc + bias (+bias2) [+relu] -> fp32 or fp16
template <bool RELU, int OUTMODE>
__device__ __forceinline__ void epilogue(
    float (&acc)[4][4][4], const float* __restrict__ bias,
    const float* __restrict__ bias2, float* __restrict__ C,
    __half* __restrict__ Ch, int bm, int bn, int wm, int wn, int lane, int Nout)
{
    float bcol[4][2];
#pragma unroll
    for (int nt = 0; nt < 4; ++nt) {
        int col = bn + wn + nt * 8 + (lane & 3) * 2;
        float b0 = bias[col], b1 = bias[col + 1];
        if (bias2) { b0 += bias2[col]; b1 += bias2[col + 1]; }
        bcol[nt][0] = b0; bcol[nt][1] = b1;
    }
#pragma unroll
    for (int mt = 0; mt < 4; ++mt) {
        int row0 = bm + wm + mt * 16 + (lane >> 2);
#pragma unroll
        for (int nt = 0; nt < 4; ++nt) {
            int col = bn + wn + nt * 8 + (lane & 3) * 2;
#pragma unroll
            for (int half = 0; half < 2; ++half) {
                int row = row0 + half * 8;
                float v0 = acc[mt][nt][half * 2 + 0] + bcol[nt][0];
                float v1 = acc[mt][nt][half * 2 + 1] + bcol[nt][1];
                if (RELU) { v0 = fmaxf(v0, 0.f); v1 = fmaxf(v1, 0.f); }
                size_t go = (size_t)row * Nout + col;
                if (OUTMODE == 1) {
                    *(uint32_t*)(Ch + go) = pack2(v0, v1);
                } else {
                    *(float2*)(C + go) = make_float2(v0, v1);
                }
            }
        }
    }
}

// ---------------------------------------------------------------------------
// Fused q/k/v projection: grid (2, 128, 3); z selects q, k(dual), v.
// ---------------------------------------------------------------------------
__global__ __launch_bounds__(256, 2)
void qkv_mma(const __half* __restrict__ tgtH, const __half* __restrict__ memH,
             const __half* __restrict__ posH,
             const __half* __restrict__ WqH, const __half* __restrict__ WkcH,
             const __half* __restrict__ WkpH, const __half* __restrict__ WvH,
             const float* __restrict__ bq, const float* __restrict__ bkc,
             const float* __restrict__ bkp, const float* __restrict__ bv,
             __half* __restrict__ q_, __half* __restrict__ k_,
             __half* __restrict__ v_)
{
    extern __shared__ char smem[];
    const uint32_t sbase = smem_u32(smem);
    const int tid = threadIdx.x;
    const int wid = tid >> 5;
    const int lane = tid & 31;
    const int bm = blockIdx.y * 128;
    const int bn = blockIdx.x * 128;
    const int wm = (wid & 1) * 64;
    const int wn = (wid >> 1) * 32;
    const int z = blockIdx.z;

    float acc[4][4][4];
#pragma unroll
    for (int a = 0; a < 4; ++a)
#pragma unroll
        for (int b = 0; b < 4; ++b)
#pragma unroll
            for (int c = 0; c < 4; ++c) acc[a][b][c] = 0.f;

    const __half* A = (z == 0) ? tgtH : memH;
    const __half* W = (z == 0) ? WqH : (z == 1) ? WkcH : WvH;
    gemm_core<8>(sbase, A, W, bm, bn, tid, wm, wn, lane, acc);
    if (z == 1)
        gemm_core<8>(sbase, posH, WkpH, bm, bn, tid, wm, wn, lane, acc);

    const float* bias = (z == 0) ? bq : (z == 1) ? bkc : bv;
    const float* bias2 = (z == 1) ? bkp : nullptr;
    __half* out = (z == 0) ? q_ : (z == 1) ? k_ : v_;
    epilogue<false, 1>(acc, bias, bias2, nullptr, out, bm, bn, wm, wn, lane, DM);
}

// ---------------------------------------------------------------------------
// Generic GEMM launch: C = A@W^T + bias
// ---------------------------------------------------------------------------
template <int CHUNKS, bool RELU, int OUTMODE>
__global__ __launch_bounds__(256, 2)
void gemm_k(const __half* __restrict__ A, const __half* __restrict__ W,
            const float* __restrict__ bias,
            float* __restrict__ C, __half* __restrict__ Ch, int Nout)
{
    extern __shared__ char smem[];
    const uint32_t sbase = smem_u32(smem);
    const int tid = threadIdx.x;
    const int wid = tid >> 5;
    const int lane = tid & 31;
    const int bm = blockIdx.y * 128;
    const int bn = blockIdx.x * 128;
    const int wm = (wid & 1) * 64;
    const int wn = (wid >> 1) * 32;

    float acc[4][4][4];
#pragma unroll
    for (int a = 0; a < 4; ++a)
#pragma unroll
        for (int b = 0; b < 4; ++b)
#pragma unroll
            for (int c = 0; c < 4; ++c) acc[a][b][c] = 0.f;

    gemm_core<CHUNKS>(sbase, A, W, bm, bn, tid, wm, wn, lane, acc);
    epilogue<RELU, OUTMODE>(acc, bias, nullptr, C, Ch, bm, bn, wm, wn, lane, Nout);
}

// ---------------------------------------------------------------------------
// Conversion: fp32 -> fp16, 10 tensors via blockIdx.y, 8 elems/thread
// ---------------------------------------------------------------------------
__global__ __launch_bounds__(256)
void conv_all(const float* s0, const float* s1, const float* s2, const float* s3,
              const float* s4, const float* s5, const float* s6, const float* s7,
              const float* s8, const float* s9, __half* dst)
{
    const int t = blockIdx.y;
    const unsigned narr[10] = {4194304u, 4194304u, 4194304u, 65536u, 65536u,
                               65536u, 65536u, 65536u, 262144u, 262144u};
    const unsigned offarr[10] = {OFF_TGT, OFF_MEM, OFF_POS, OFF_WQ, OFF_WKC,
                                 OFF_WKP, OFF_WV, OFF_WO, OFF_W1, OFF_W2};
    const float* srcs[10] = {s0, s1, s2, s3, s4, s5, s6, s7, s8, s9};
    unsigned i = (blockIdx.x * 256u + threadIdx.x) * 8u;
    if (i >= narr[t]) return;
    const float* src = srcs[t];
    float4 v0 = *(const float4*)(src + i);
    float4 v1 = *(const float4*)(src + i + 4);
    uint4 o;
    o.x = pack2(v0.x, v0.y);
    o.y = pack2(v0.z, v0.w);
    o.z = pack2(v1.x, v1.y);
    o.w = pack2(v1.z, v1.w);
    *(uint4*)(dst + offarr[t] + i) = o;
}

// ---------------------------------------------------------------------------
// Local attention: one warp per query; q/k/v fp16, output fp16.
// ---------------------------------------------------------------------------
__global__ __launch_bounds__(256, 2)
void attn_kernel(const __half* __restrict__ q, const __half* __restrict__ k,
                 const __half* __restrict__ v, const int* __restrict__ kbc,
                 const int* __restrict__ ipair, const int* __restrict__ ibatch,
                 __half* __restrict__ oat)
{
    __shared__ int sg[8][32];
    const int warp = threadIdx.x >> 5;
    const int lane = threadIdx.x & 31;
    const int n = blockIdx.x * 8 + warp;
    const int h = lane >> 2;
    const int s = lane & 3;
    const int doff = h * 32 + s * 8;

    int b = ibatch[n];
    int off = 0;
    for (int i = 0; i < b; ++i) off += kbc[i];

    int idx = ipair[n * 32 + lane];
    unsigned mb = __ballot_sync(0xffffffffu, idx < 0);
    sg[warp][lane] = ((idx < 0) ? 0 : idx) + off;
    __syncwarp();

    const float scale = 0.17677669529663687f;
    float qr[8];
    {
        uint4 raw = *(const uint4*)&q[(size_t)n * 256 + doff];
        float2 a0 = __half22float2(*(__half2*)&raw.x);
        float2 a1 = __half22float2(*(__half2*)&raw.y);
        float2 a2 = __half22float2(*(__half2*)&raw.z);
        float2 a3 = __half22float2(*(__half2*)&raw.w);
        qr[0] = a0.x * scale; qr[1] = a0.y * scale;
        qr[2] = a1.x * scale; qr[3] = a1.y * scale;
        qr[4] = a2.x * scale; qr[5] = a2.y * scale;
        qr[6] = a3.x * scale; qr[7] = a3.y * scale;
    }

    float lg[32];
#pragma unroll
    for (int j = 0; j < 32; ++j) {
        uint4 raw = *(const uint4*)&k[(size_t)sg[warp][j] * 256 + doff];
        float2 a0 = __half22float2(*(__half2*)&raw.x);
        float2 a1 = __half22float2(*(__half2*)&raw.y);
        float2 a2 = __half22float2(*(__half2*)&raw.z);
        float2 a3 = __half22float2(*(__half2*)&raw.w);
        float t = qr[0] * a0.x + qr[1] * a0.y + qr[2] * a1.x + qr[3] * a1.y
                + qr[4] * a2.x + qr[5] * a2.y + qr[6] * a3.x + qr[7] * a3.y;
        t += __shfl_xor_sync(0xffffffffu, t, 1);
        t += __shfl_xor_sync(0xffffffffu, t, 2);
        lg[j] = ((mb >> j) & 1u) ? -1e9f : t;
    }

    float m = lg[0];
#pragma unroll
    for (int j = 1; j < 32; ++j) m = fmaxf(m, lg[j]);
    float sum = 0.f;
#pragma unroll
    for (int j = 0; j < 32; ++j) { lg[j] = __expf(lg[j] - m); sum += lg[j]; }
    float rinv = 1.f / sum;

    float acc[8];
#pragma unroll
    for (int i = 0; i < 8; ++i) acc[i] = 0.f;
#pragma unroll
    for (int j = 0; j < 32; ++j) {
        uint4 raw = *(const uint4*)&v[(size_t)sg[warp][j] * 256 + doff];
        float2 a0 = __half22float2(*(__half2*)&raw.x);
        float2 a1 = __half22float2(*(__half2*)&raw.y);
        float2 a2 = __half22float2(*(__half2*)&raw.z);
        float2 a3 = __half22float2(*(__half2*)&raw.w);
        float p = lg[j] * rinv;
        acc[0] += p * a0.x; acc[1] += p * a0.y; acc[2] += p * a1.x; acc[3] += p * a1.y;
        acc[4] += p * a2.x; acc[5] += p * a2.y; acc[6] += p * a3.x; acc[7] += p * a3.y;
    }

    uint4 o;
    o.x = pack2(acc[0], acc[1]);
    o.y = pack2(acc[2], acc[3]);
    o.z = pack2(acc[4], acc[5]);
    o.w = pack2(acc[6], acc[7]);
    *(uint4*)(oat + (size_t)n * 256 + doff) = o;
}

// ---------------------------------------------------------------------------
// out = LayerNorm(a + b); optionally also writes fp16 copy.
// ---------------------------------------------------------------------------
template <bool OUTH>
__global__ __launch_bounds__(256)
void residual_ln(const float* __restrict__ a, const float* __restrict__ bsrc,
                 const float* __restrict__ g, const float* __restrict__ be,
                 float* __restrict__ out, __half* __restrict__ oh)
{
    const int warp = threadIdx.x >> 5;
    const int lane = threadIdx.x & 31;
    const int n = blockIdx.x * 8 + warp;
    const int base = lane * 8;

    float x[8];
    {
        const float4* pa0 = (const float4*)&a[(size_t)n * 256 + base];
        const float4* pb0 = (const float4*)&bsrc[(size_t)n * 256 + base];
        float4 a0 = pa0[0], a1 = pa0[1];
        float4 b0 = pb0[0], b1 = pb0[1];
        x[0] = a0.x + b0.x; x[1] = a0.y + b0.y; x[2] = a0.z + b0.z; x[3] = a0.w + b0.w;
        x[4] = a1.x + b1.x; x[5] = a1.y + b1.y; x[6] = a1.z + b1.z; x[7] = a1.w + b1.w;
    }
    float s = 0.f;
#pragma unroll
    for (int i = 0; i < 8; ++i) s += x[i];
#pragma unroll
    for (int o = 16; o > 0; o >>= 1) s += __shfl_xor_sync(0xffffffffu, s, o);
    float mean = s * (1.f / 256.f);

    float vs = 0.f;
#pragma unroll
    for (int i = 0; i < 8; ++i) { float d = x[i] - mean; vs += d * d; }
#pragma unroll
    for (int o = 16; o > 0; o >>= 1) vs += __shfl_xor_sync(0xffffffffu, vs, o);
    float inv = rsqrtf(vs * (1.f / 256.f) + LN_EPS);

    float4 gg0 = *(const float4*)&g[base];
    float4 gg1 = *(const float4*)&g[base + 4];
    float4 bb0 = *(const float4*)&be[base];
    float4 bb1 = *(const float4*)&be[base + 4];

    float r[8];
    r[0] = (x[0] - mean) * inv * gg0.x + bb0.x;
    r[1] = (x[1] - mean) * inv * gg0.y + bb0.y;
    r[2] = (x[2] - mean) * inv * gg0.z + bb0.z;
    r[3] = (x[3] - mean) * inv * gg0.w + bb0.w;
    r[4] = (x[4] - mean) * inv * gg1.x + bb1.x;
    r[5] = (x[5] - mean) * inv * gg1.y + bb1.y;
    r[6] = (x[6] - mean) * inv * gg1.z + bb1.z;
    r[7] = (x[7] - mean) * inv * gg1.w + bb1.w;

    size_t o = (size_t)n * 256 + base;
    *(float4*)(out + o) = make_float4(r[0], r[1], r[2], r[3]);
    *(float4*)(out + o + 4) = make_float4(r[4], r[5], r[6], r[7]);

    if (OUTH) {
        uint4 p;
        p.x = pack2(r[0], r[1]);
        p.y = pack2(r[2], r[3]);
        p.z = pack2(r[4], r[5]);
        p.w = pack2(r[6], r[7]);
        *(uint4*)(oh + o) = p;
    }
}

// ---------------------------------------------------------------------------
extern "C" void kernel_launch(void* const* d_in, const int* in_sizes, int n_in,
                              void* d_out, int out_size)
{
    const float* tgt  = (const float*)d_in[0];
    const float* mem  = (const float*)d_in[1];
    const float* pos  = (const float*)d_in[2];
    const int*   kbc  = (const int*)d_in[3];
    const int*   ipair  = (const int*)d_in[4];
    const int*   ibatch = (const int*)d_in[5];
    const float* Wq  = (const float*)d_in[6];
    const float* bq  = (const float*)d_in[7];
    const float* Wkc = (const float*)d_in[8];
    const float* bkc = (const float*)d_in[9];
    const float* Wkp = (const float*)d_in[10];
    const float* bkp = (const float*)d_in[11];
    const float* Wv  = (const float*)d_in[12];
    const float* bv  = (const float*)d_in[13];
    const float* Wo  = (const float*)d_in[14];
    const float* bo  = (const float*)d_in[15];
    const float* W1  = (const float*)d_in[16];
    const float* b1  = (const float*)d_in[17];
    const float* W2  = (const float*)d_in[18];
    const float* b2  = (const float*)d_in[19];
    const float* g2  = (const float*)d_in[20];
    const float* be2 = (const float*)d_in[21];
    const float* g3  = (const float*)d_in[22];
    const float* be3 = (const float*)d_in[23];
    float* out = (float*)d_out;

    float* f32 = nullptr;
    __half* qkv = nullptr;
    __half* h16 = nullptr;
    cudaGetSymbolAddress((void**)&f32, g_f32);
    cudaGetSymbolAddress((void**)&qkv, g_qkv);
    cudaGetSymbolAddress((void**)&h16, g_h16);

    float* t2_ = f32 + 0u * NQ * DM;
    float* x_  = f32 + 1u * NQ * DM;
    __half* q_ = qkv + 0u * NQ * DM;
    __half* k_ = qkv + 1u * NQ * DM;
    __half* v_ = qkv + 2u * NQ * DM;

    cudaFuncSetAttribute(qkv_mma,
                         cudaFuncAttributeMaxDynamicSharedMemorySize, SMEM_BYTES);
    cudaFuncSetAttribute(gemm_k<8, false, 0>,
                         cudaFuncAttributeMaxDynamicSharedMemorySize, SMEM_BYTES);
    cudaFuncSetAttribute(gemm_k<8, true, 1>,
                         cudaFuncAttributeMaxDynamicSharedMemorySize, SMEM_BYTES);
    cudaFuncSetAttribute(gemm_k<32, false, 0>,
                         cudaFuncAttributeMaxDynamicSharedMemorySize, SMEM_BYTES);

    // converts (fp32 -> fp16)
    conv_all<<<dim3(2048, 10), 256>>>(tgt, mem, pos, Wq, Wkc, Wkp, Wv, Wo, W1, W2, h16);

    dim3 blk(256);

    // fused q/k/v projections (fp16 out)
    qkv_mma<<<dim3(2, 128, 3), blk, SMEM_BYTES>>>(
        h16 + OFF_TGT, h16 + OFF_MEM, h16 + OFF_POS,
        h16 + OFF_WQ, h16 + OFF_WKC, h16 + OFF_WKP, h16 + OFF_WV,
        bq, bkc, bkp, bv, q_, k_, v_);
    // attention -> at (fp16)
    attn_kernel<<<NQ / 8, blk>>>(q_, k_, v_, kbc, ipair, ibatch, h16 + OFF_AT);
    // t2 = at @ Wo^T + bo  (fp32 out)
    gemm_k<8, false, 0><<<dim3(2, 128), blk, SMEM_BYTES>>>(
        h16 + OFF_AT, h16 + OFF_WO, bo, t2_, nullptr, DM);
    // x = LN(tgt + t2), also fp16 copy
    residual_ln<true><<<NQ / 8, blk>>>(tgt, t2_, g2, be2, x_, h16 + OFF_X);
    // h = relu(x @ W1^T + b1)  (fp16 out)
    gemm_k<8, true, 1><<<dim3(8, 128), blk, SMEM_BYTES>>>(
        h16 + OFF_X, h16 + OFF_W1, b1, nullptr, h16 + OFF_H, DFF_);
    // y = h @ W2^T + b2  (fp32 out)
    gemm_k<32, false, 0><<<dim3(2, 128), blk, SMEM_BYTES>>>(
        h16 + OFF_H, h16 + OFF_W2, b2, t2_, nullptr, DM);
    // out = LN(x + y)
    residual_ln<false><<<NQ / 8, blk>>>(x_, t2_, g3, be3, out, nullptr);
}